// round 1
// baseline (speedup 1.0000x reference)
#include <cuda_runtime.h>
#include <math.h>

// Problem dims (fixed per setup_inputs)
#define B_   4
#define T_   4096
#define DIN  1024
#define D_   1024
#define M_   (B_*T_)        // 16384

// ---------------- scratch (device globals; no allocations allowed) ---------
__device__ float g_buf0[(size_t)M_ * D_];   // 64 MB
__device__ float g_buf1[(size_t)M_ * D_];   // 64 MB
__device__ float g_buf2[(size_t)M_ * D_];   // 64 MB

#define CHUNK 32
#define NC    (T_/CHUNK)    // 128
__device__ float g_cA[B_*NC*D_];   // per-chunk product of f
__device__ float g_cP[B_*NC*D_];   // per-chunk partial (h from 0)
__device__ float g_cC[B_*NC*D_];   // per-chunk carry-in

// ---------------- fp32 tiled GEMM with fused epilogues ---------------------
#define BM 128
#define BN 128
#define BK 8
#define TM 8
#define TN 8
#define GEMM_THREADS 256

enum { MODE_TANH = 0, MODE_SIGF = 1, MODE_BIAS = 2, MODE_GELU = 3, MODE_RESID = 4 };

template <int MODE>
__global__ __launch_bounds__(GEMM_THREADS)
void sgemm_ep(int M, int N, int K,
              const float* __restrict__ A,      // [M,K] row-major
              const float* __restrict__ Bm,     // [K,N] row-major
              const float* __restrict__ bias,   // [N]
              const float* __restrict__ extra,  // rnn_start [M] (SIGF) or residual [M,N] (RESID)
              float* __restrict__ C)            // [M,N]
{
    __shared__ float As[BK][BM];
    __shared__ float Bs[BK][BN];

    const int tid = threadIdx.x;
    const int bm  = blockIdx.y;
    const int bn  = blockIdx.x;

    const float* Ab = A  + (size_t)bm * BM * K;
    const float* Bb = Bm + (size_t)bn * BN;

    const int arow = tid >> 1;          // 0..127
    const int acol = (tid & 1) << 2;    // 0 or 4
    const int brow = tid >> 5;          // 0..7
    const int bcol = (tid & 31) << 2;   // 0..124
    const int trow = (tid >> 4) * TM;   // row base in tile
    const int tcol = (tid & 15) * TN;   // col base in tile

    float acc[TM][TN];
#pragma unroll
    for (int i = 0; i < TM; i++)
#pragma unroll
        for (int j = 0; j < TN; j++) acc[i][j] = 0.f;

    for (int k0 = 0; k0 < K; k0 += BK) {
        float4 a4 = *reinterpret_cast<const float4*>(Ab + (size_t)arow * K + k0 + acol);
        As[acol + 0][arow] = a4.x;
        As[acol + 1][arow] = a4.y;
        As[acol + 2][arow] = a4.z;
        As[acol + 3][arow] = a4.w;
        float4 b4 = *reinterpret_cast<const float4*>(Bb + (size_t)(k0 + brow) * N + bcol);
        *reinterpret_cast<float4*>(&Bs[brow][bcol]) = b4;
        __syncthreads();

#pragma unroll
        for (int kk = 0; kk < BK; kk++) {
            float ra[TM], rb[TN];
#pragma unroll
            for (int i = 0; i < TM; i++) ra[i] = As[kk][trow + i];
#pragma unroll
            for (int j = 0; j < TN; j++) rb[j] = Bs[kk][tcol + j];
#pragma unroll
            for (int i = 0; i < TM; i++)
#pragma unroll
                for (int j = 0; j < TN; j++)
                    acc[i][j] = fmaf(ra[i], rb[j], acc[i][j]);
        }
        __syncthreads();
    }

    const int gc0 = bn * BN + tcol;
#pragma unroll
    for (int i = 0; i < TM; i++) {
        const int gr = bm * BM + trow + i;
        float rs = 0.f;
        if (MODE == MODE_SIGF) rs = extra[gr];
#pragma unroll
        for (int j = 0; j < TN; j++) {
            float v = acc[i][j] + bias[gc0 + j];
            if (MODE == MODE_TANH) {
                v = tanhf(v);
            } else if (MODE == MODE_SIGF) {
                v = 1.f / (1.f + expf(-v));
                v *= (1.f - rs);
            } else if (MODE == MODE_GELU) {
                v = 0.5f * v * (1.f + erff(v * 0.70710678118654752f));
            } else if (MODE == MODE_RESID) {
                v += extra[(size_t)gr * N + gc0 + j];
            }
            C[(size_t)gr * N + gc0 + j] = v;
        }
    }
}

// ---------------- chunked scan: h_t = f_t * h_{t-1} + (1-f_t) * v_t --------
__global__ void scan_pass1(const float* __restrict__ V, const float* __restrict__ F)
{
    int idx = blockIdx.x * blockDim.x + threadIdx.x;   // over B*NC*D
    int d = idx % D_;
    int c = (idx / D_) % NC;
    int b = idx / (D_ * NC);
    size_t base = ((size_t)b * T_ + (size_t)c * CHUNK) * D_ + d;
    float A = 1.f, h = 0.f;
#pragma unroll 8
    for (int t = 0; t < CHUNK; t++) {
        float f = F[base + (size_t)t * D_];
        float v = V[base + (size_t)t * D_];
        A *= f;
        h = f * h + (1.f - f) * v;
    }
    g_cA[idx] = A;
    g_cP[idx] = h;
}

__global__ void scan_pass2(const float* __restrict__ hidden, float* __restrict__ hT_out)
{
    int idx = blockIdx.x * blockDim.x + threadIdx.x;   // over B*D
    int d = idx % D_;
    int b = idx / D_;
    float h = hidden[(size_t)b * D_ + d];
    for (int c = 0; c < NC; c++) {
        size_t o = ((size_t)b * NC + c) * D_ + d;
        g_cC[o] = h;
        h = g_cA[o] * h + g_cP[o];
    }
    hT_out[(size_t)b * D_ + d] = h;   // hidden_new = hT
}

__global__ void scan_pass3(const float* __restrict__ V, const float* __restrict__ F,
                           float* __restrict__ HS)
{
    int idx = blockIdx.x * blockDim.x + threadIdx.x;   // over B*NC*D
    int d = idx % D_;
    int c = (idx / D_) % NC;
    int b = idx / (D_ * NC);
    size_t base = ((size_t)b * T_ + (size_t)c * CHUNK) * D_ + d;
    float h = g_cC[idx];
#pragma unroll 8
    for (int t = 0; t < CHUNK; t++) {
        float f = F[base + (size_t)t * D_];
        float v = V[base + (size_t)t * D_];
        h = f * h + (1.f - f) * v;
        HS[base + (size_t)t * D_] = h;
    }
}

// ---------------- LayerNorm over last axis (row = 1024 floats) -------------
__global__ __launch_bounds__(256)
void ln_kernel(const float* __restrict__ Z, const float* __restrict__ g,
               const float* __restrict__ b, float* __restrict__ out)
{
    int row = blockIdx.x;
    int t = threadIdx.x;   // 256 threads * float4 = 1024 elems
    float4 x = reinterpret_cast<const float4*>(Z + (size_t)row * D_)[t];
    float s  = x.x + x.y + x.z + x.w;
    float ss = x.x * x.x + x.y * x.y + x.z * x.z + x.w * x.w;

#pragma unroll
    for (int o = 16; o > 0; o >>= 1) {
        s  += __shfl_xor_sync(0xFFFFFFFFu, s, o);
        ss += __shfl_xor_sync(0xFFFFFFFFu, ss, o);
    }
    __shared__ float sh_s[8], sh_ss[8];
    int w = t >> 5, l = t & 31;
    if (l == 0) { sh_s[w] = s; sh_ss[w] = ss; }
    __syncthreads();
    if (w == 0) {
        s  = (l < 8) ? sh_s[l]  : 0.f;
        ss = (l < 8) ? sh_ss[l] : 0.f;
#pragma unroll
        for (int o = 4; o > 0; o >>= 1) {
            s  += __shfl_xor_sync(0xFFFFFFFFu, s, o);
            ss += __shfl_xor_sync(0xFFFFFFFFu, ss, o);
        }
        if (l == 0) { sh_s[0] = s; sh_ss[0] = ss; }
    }
    __syncthreads();
    float mean = sh_s[0] * (1.f / D_);
    float var  = sh_ss[0] * (1.f / D_) - mean * mean;
    float rstd = rsqrtf(var + 1e-5f);

    float4 gg = reinterpret_cast<const float4*>(g)[t];
    float4 bb = reinterpret_cast<const float4*>(b)[t];
    float4 y;
    y.x = (x.x - mean) * rstd * gg.x + bb.x;
    y.y = (x.y - mean) * rstd * gg.y + bb.y;
    y.z = (x.z - mean) * rstd * gg.z + bb.z;
    y.w = (x.w - mean) * rstd * gg.w + bb.w;
    reinterpret_cast<float4*>(out + (size_t)row * D_)[t] = y;
}

// ---------------- launch ---------------------------------------------------
extern "C" void kernel_launch(void* const* d_in, const int* in_sizes, int n_in,
                              void* d_out, int out_size)
{
    const float* x         = (const float*)d_in[0];   // [B,T,Din]
    const float* hidden    = (const float*)d_in[1];   // [B,1,D]
    const float* rnn_start = (const float*)d_in[2];   // [B,T,1]
    const float* Win       = (const float*)d_in[3];   // [2,Din,D]
    const float* bin_      = (const float*)d_in[4];   // [2,D]
    const float* Wout      = (const float*)d_in[5];   // [D,D]
    const float* bout      = (const float*)d_in[6];   // [D]
    const float* W1        = (const float*)d_in[7];   // [D,D]
    const float* b1        = (const float*)d_in[8];   // [D]
    const float* W2        = (const float*)d_in[9];   // [D,D]
    const float* b2        = (const float*)d_in[10];  // [D]
    const float* ln_g      = (const float*)d_in[11];  // [D]
    const float* ln_b      = (const float*)d_in[12];  // [D]

    float* out        = (float*)d_out;                 // [B,T,D]
    float* hidden_out = out + (size_t)M_ * D_;         // [1,B,D]

    float *buf0, *buf1, *buf2;
    cudaGetSymbolAddress((void**)&buf0, g_buf0);
    cudaGetSymbolAddress((void**)&buf1, g_buf1);
    cudaGetSymbolAddress((void**)&buf2, g_buf2);

    dim3 grid(D_ / BN, M_ / BM);   // (8, 128)

    // u0 -> v = tanh(x@Win[0]+bin[0]);  u1 -> f = sigmoid(x@Win[1]+bin[1])*(1-rnn_start)
    sgemm_ep<MODE_TANH><<<grid, GEMM_THREADS>>>(M_, D_, DIN, x, Win, bin_, nullptr, buf0);
    sgemm_ep<MODE_SIGF><<<grid, GEMM_THREADS>>>(M_, D_, DIN, x, Win + (size_t)DIN * D_,
                                                bin_ + D_, rnn_start, buf1);

    // chunked scan -> hs in buf2, hT -> hidden_out
    scan_pass1<<<(B_ * NC * D_) / 256, 256>>>(buf0, buf1);
    scan_pass2<<<(B_ * D_) / 256, 256>>>(hidden, hidden_out);
    scan_pass3<<<(B_ * NC * D_) / 256, 256>>>(buf0, buf1, buf2);

    // out = hs@Wout + bout        (buf2 -> buf0)
    sgemm_ep<MODE_BIAS><<<grid, GEMM_THREADS>>>(M_, D_, D_, buf2, Wout, bout, nullptr, buf0);
    // x_ = gelu(out@W1 + b1)      (buf0 -> buf1)
    sgemm_ep<MODE_GELU><<<grid, GEMM_THREADS>>>(M_, D_, D_, buf0, W1, b1, nullptr, buf1);
    // z = x_@W2 + b2 + out        (buf1 + buf0 -> buf2)
    sgemm_ep<MODE_RESID><<<grid, GEMM_THREADS>>>(M_, D_, D_, buf1, W2, b2, buf0, buf2);
    // out = LN(z)*g + b
    ln_kernel<<<M_, 256>>>(buf2, ln_g, ln_b, out);
}

// round 3
// speedup vs baseline: 3.3360x; 3.3360x over previous
#include <cuda_runtime.h>
#include <math.h>
#include <stdint.h>

// Problem dims (fixed per setup_inputs)
#define B_   4
#define T_   4096
#define K_   1024          // Din == D == 1024
#define D_   1024
#define M_   (B_*T_)       // 16384

// ---------------- scratch (device globals; no allocations allowed) ---------
__device__ float g_buf0[(size_t)M_ * D_];   // 64 MB
__device__ float g_buf1[(size_t)M_ * D_];   // 64 MB
__device__ float g_buf2[(size_t)M_ * D_];   // 64 MB
__device__ float g_wT[(size_t)5 * K_ * D_]; // 20 MB transposed + tf32-rounded weights

#define CHUNK 32
#define NC    (T_/CHUNK)    // 128
__device__ float g_cA[B_*NC*D_];
__device__ float g_cP[B_*NC*D_];
__device__ float g_cC[B_*NC*D_];

// ---------------- helpers ----------------------------------------------------
__device__ __forceinline__ uint32_t cvt_tf32(float x) {
    uint32_t t; asm("cvt.rna.tf32.f32 %0, %1;" : "=r"(t) : "f"(x)); return t;
}

// ---------------- tf32 mma.sync GEMM: C[M,1024] = A[M,1024] @ Bt^T -----------
// Bt is [N=1024, K=1024] row-major (row = output col, K contiguous), tf32 bits.
// CTA tile 128x128, BK=32 double-buffered; 8 warps (2 M x 4 N), warp 64x32.

#define BMm 128
#define BNm 128
#define BKm 32
#define STEPSm (K_/BKm)        // 32
#define SROW  36               // padded row stride (words): conflict-free frags
#define STAGE_WORDS (BMm*SROW) // per-matrix per-stage
#define GEMM_SMEM (4*STAGE_WORDS*4)   // A0,A1,B0,B1 = 73728 B

enum { MODE_TANH = 0, MODE_SIGF = 1, MODE_BIAS = 2, MODE_GELU = 3, MODE_RESID = 4 };

__device__ __forceinline__ void mma_tf32(float c[4], const uint32_t a[4], const uint32_t b[2]) {
    asm volatile(
        "mma.sync.aligned.m16n8k8.row.col.f32.tf32.tf32.f32 "
        "{%0,%1,%2,%3}, {%4,%5,%6,%7}, {%8,%9}, {%0,%1,%2,%3};"
        : "+f"(c[0]), "+f"(c[1]), "+f"(c[2]), "+f"(c[3])
        : "r"(a[0]), "r"(a[1]), "r"(a[2]), "r"(a[3]), "r"(b[0]), "r"(b[1]));
}

template <int MODE>
__global__ __launch_bounds__(256)
void tgemm(const float* __restrict__ A,       // [M,1024] fp32
           const float* __restrict__ Bt,      // [1024,1024] tf32 bits, N-major
           const float* __restrict__ bias,    // [1024]
           const float* __restrict__ extra,   // rnn_start[M] (SIGF) or residual[M,1024] (RESID)
           float* __restrict__ C)             // [M,1024]
{
    extern __shared__ float sm[];
    float* sA = sm;                     // [2][STAGE_WORDS]
    float* sB = sm + 2 * STAGE_WORDS;   // [2][STAGE_WORDS]

    const int tid  = threadIdx.x;
    const int lane = tid & 31;
    const int wid  = tid >> 5;
    const int wm   = wid >> 2;          // 0..1
    const int wn   = wid & 3;           // 0..3
    const int bn   = blockIdx.x;        // 0..7
    const int bm   = blockIdx.y;        // 0..127

    const float* Ab = A  + (size_t)bm * BMm * K_;
    const float* Bb = Bt + (size_t)bn * BNm * K_;

    // global->smem mapping: 4 float4 per thread per matrix per stage
    const int grow = tid >> 3;          // f>>3 for f=tid..  (recomputed per j)
    (void)grow;

    float acc[4][4][4];
#pragma unroll
    for (int mi = 0; mi < 4; mi++)
#pragma unroll
        for (int ni = 0; ni < 4; ni++)
#pragma unroll
            for (int q = 0; q < 4; q++) acc[mi][ni][q] = 0.f;

    // fragment base offsets (word indices within a stage)
    const int ar = wm * 64 + (lane >> 2);     // + mi*16, +8
    const int ak = lane & 3;                  // + k0, +4
    const int br = wn * 32 + (lane >> 2);     // + ni*8
    const int bk = lane & 3;

    // ---- stage 0 fill
#pragma unroll
    for (int j = 0; j < 4; j++) {
        int f = tid + 256 * j;
        int row = f >> 3, c4 = (f & 7) << 2;
        float4 va = *reinterpret_cast<const float4*>(Ab + (size_t)row * K_ + c4);
        float4 sa;
        sa.x = __uint_as_float(cvt_tf32(va.x));
        sa.y = __uint_as_float(cvt_tf32(va.y));
        sa.z = __uint_as_float(cvt_tf32(va.z));
        sa.w = __uint_as_float(cvt_tf32(va.w));
        *reinterpret_cast<float4*>(&sA[row * SROW + c4]) = sa;
        float4 vb = *reinterpret_cast<const float4*>(Bb + (size_t)row * K_ + c4);
        *reinterpret_cast<float4*>(&sB[row * SROW + c4]) = vb;
    }
    __syncthreads();

    int cur = 0;
    for (int s = 0; s < STEPSm; s++) {
        float4 pa[4], pb[4];
        const bool more = (s + 1 < STEPSm);
        if (more) {
            const int k0 = (s + 1) * BKm;
#pragma unroll
            for (int j = 0; j < 4; j++) {
                int f = tid + 256 * j;
                int row = f >> 3, c4 = (f & 7) << 2;
                pa[j] = *reinterpret_cast<const float4*>(Ab + (size_t)row * K_ + k0 + c4);
                pb[j] = *reinterpret_cast<const float4*>(Bb + (size_t)row * K_ + k0 + c4);
            }
        }

        const uint32_t* cA = reinterpret_cast<const uint32_t*>(sA + cur * STAGE_WORDS);
        const uint32_t* cB = reinterpret_cast<const uint32_t*>(sB + cur * STAGE_WORDS);
#pragma unroll
        for (int ks = 0; ks < 4; ks++) {
            const int k0 = ks * 8;
            uint32_t afr[4][4];
#pragma unroll
            for (int mi = 0; mi < 4; mi++) {
                const uint32_t* p = cA + (ar + mi * 16) * SROW + k0 + ak;
                afr[mi][0] = p[0];
                afr[mi][1] = p[8 * SROW];
                afr[mi][2] = p[4];
                afr[mi][3] = p[8 * SROW + 4];
            }
            uint32_t bfr[4][2];
#pragma unroll
            for (int ni = 0; ni < 4; ni++) {
                const uint32_t* p = cB + (br + ni * 8) * SROW + k0 + bk;
                bfr[ni][0] = p[0];
                bfr[ni][1] = p[4];
            }
#pragma unroll
            for (int mi = 0; mi < 4; mi++)
#pragma unroll
                for (int ni = 0; ni < 4; ni++)
                    mma_tf32(acc[mi][ni], afr[mi], bfr[ni]);
        }

        if (more) {
            float* nA = sA + (cur ^ 1) * STAGE_WORDS;
            float* nB = sB + (cur ^ 1) * STAGE_WORDS;
#pragma unroll
            for (int j = 0; j < 4; j++) {
                int f = tid + 256 * j;
                int row = f >> 3, c4 = (f & 7) << 2;
                float4 sa;
                sa.x = __uint_as_float(cvt_tf32(pa[j].x));
                sa.y = __uint_as_float(cvt_tf32(pa[j].y));
                sa.z = __uint_as_float(cvt_tf32(pa[j].z));
                sa.w = __uint_as_float(cvt_tf32(pa[j].w));
                *reinterpret_cast<float4*>(&nA[row * SROW + c4]) = sa;
                *reinterpret_cast<float4*>(&nB[row * SROW + c4]) = pb[j];
            }
        }
        __syncthreads();
        cur ^= 1;
    }

    // ---- fused epilogue
    const int r_base = bm * BMm + wm * 64 + (lane >> 2);
    const int c_base = bn * BNm + wn * 32 + ((lane & 3) << 1);
#pragma unroll
    for (int mi = 0; mi < 4; mi++) {
        const int r0 = r_base + mi * 16;
        const int r1 = r0 + 8;
        float rs0 = 0.f, rs1 = 0.f;
        if (MODE == MODE_SIGF) { rs0 = extra[r0]; rs1 = extra[r1]; }
#pragma unroll
        for (int ni = 0; ni < 4; ni++) {
            const int gc = c_base + ni * 8;
            float b0 = bias[gc], b1 = bias[gc + 1];
            float v0 = acc[mi][ni][0] + b0;
            float v1 = acc[mi][ni][1] + b1;
            float v2 = acc[mi][ni][2] + b0;
            float v3 = acc[mi][ni][3] + b1;
            if (MODE == MODE_TANH) {
                v0 = tanhf(v0); v1 = tanhf(v1); v2 = tanhf(v2); v3 = tanhf(v3);
            } else if (MODE == MODE_SIGF) {
                v0 = (1.f - rs0) / (1.f + expf(-v0));
                v1 = (1.f - rs0) / (1.f + expf(-v1));
                v2 = (1.f - rs1) / (1.f + expf(-v2));
                v3 = (1.f - rs1) / (1.f + expf(-v3));
            } else if (MODE == MODE_GELU) {
                v0 = 0.5f * v0 * (1.f + erff(v0 * 0.70710678118654752f));
                v1 = 0.5f * v1 * (1.f + erff(v1 * 0.70710678118654752f));
                v2 = 0.5f * v2 * (1.f + erff(v2 * 0.70710678118654752f));
                v3 = 0.5f * v3 * (1.f + erff(v3 * 0.70710678118654752f));
            } else if (MODE == MODE_RESID) {
                const float2 e0 = *reinterpret_cast<const float2*>(extra + (size_t)r0 * D_ + gc);
                const float2 e1 = *reinterpret_cast<const float2*>(extra + (size_t)r1 * D_ + gc);
                v0 += e0.x; v1 += e0.y; v2 += e1.x; v3 += e1.y;
            }
            *reinterpret_cast<float2*>(C + (size_t)r0 * D_ + gc) = make_float2(v0, v1);
            *reinterpret_cast<float2*>(C + (size_t)r1 * D_ + gc) = make_float2(v2, v3);
        }
    }
}

// ---------------- weight transpose + tf32 rounding --------------------------
__global__ void transpose_tf32(const float* __restrict__ s0, const float* __restrict__ s1,
                               const float* __restrict__ s2, const float* __restrict__ s3,
                               const float* __restrict__ s4, float* __restrict__ dst)
{
    __shared__ float tile[32][33];
    const int z = blockIdx.z;
    const float* src = (z == 0) ? s0 : (z == 1) ? s1 : (z == 2) ? s2 : (z == 3) ? s3 : s4;
    float* d = dst + (size_t)z * K_ * D_;
    const int n0 = blockIdx.x * 32, k0 = blockIdx.y * 32;
    const int tx = threadIdx.x, ty = threadIdx.y;   // 32x8
#pragma unroll
    for (int r = 0; r < 32; r += 8)
        tile[ty + r][tx] = src[(size_t)(k0 + ty + r) * D_ + n0 + tx];
    __syncthreads();
#pragma unroll
    for (int r = 0; r < 32; r += 8) {
        uint32_t t = cvt_tf32(tile[tx][ty + r]);
        d[(size_t)(n0 + ty + r) * K_ + k0 + tx] = __uint_as_float(t);
    }
}

// ---------------- chunked scan: h_t = f_t*h_{t-1} + (1-f_t)*v_t -------------
__global__ void scan_pass1(const float* __restrict__ V, const float* __restrict__ F)
{
    int idx = blockIdx.x * blockDim.x + threadIdx.x;
    int d = idx % D_;
    int c = (idx / D_) % NC;
    int b = idx / (D_ * NC);
    size_t base = ((size_t)b * T_ + (size_t)c * CHUNK) * D_ + d;
    float A = 1.f, h = 0.f;
#pragma unroll 8
    for (int t = 0; t < CHUNK; t++) {
        float f = F[base + (size_t)t * D_];
        float v = V[base + (size_t)t * D_];
        A *= f;
        h = f * h + (1.f - f) * v;
    }
    g_cA[idx] = A;
    g_cP[idx] = h;
}

// stage chunk coefficients in SMEM; serial recurrence hits SMEM not DRAM
__global__ void scan_pass2(const float* __restrict__ hidden, float* __restrict__ hT_out)
{
    extern __shared__ float sh[];          // sA[128*128], sP[128*128] = 128KB
    float* sA = sh;
    float* sP = sh + NC * 128;
    const int blk = blockIdx.x;            // 32 blocks
    const int b   = blk >> 3;
    const int d0  = (blk & 7) * 128;
#pragma unroll 4
    for (int j = 0; j < 64; j++) {         // 16384 elems / 256 threads
        int i  = threadIdx.x + 256 * j;
        int c  = i >> 7, dd = i & 127;
        size_t g = ((size_t)b * NC + c) * D_ + d0 + dd;
        sA[i] = g_cA[g];
        sP[i] = g_cP[g];
    }
    __syncthreads();
    if (threadIdx.x < 128) {
        const int dd = threadIdx.x;
        float h = hidden[(size_t)b * D_ + d0 + dd];
        for (int c = 0; c < NC; c++) {
            g_cC[((size_t)b * NC + c) * D_ + d0 + dd] = h;
            h = sA[c * 128 + dd] * h + sP[c * 128 + dd];
        }
        hT_out[(size_t)b * D_ + d0 + dd] = h;
    }
}

__global__ void scan_pass3(const float* __restrict__ V, const float* __restrict__ F,
                           float* __restrict__ HS)
{
    int idx = blockIdx.x * blockDim.x + threadIdx.x;
    int d = idx % D_;
    int c = (idx / D_) % NC;
    int b = idx / (D_ * NC);
    size_t base = ((size_t)b * T_ + (size_t)c * CHUNK) * D_ + d;
    float h = g_cC[idx];
#pragma unroll 8
    for (int t = 0; t < CHUNK; t++) {
        float f = F[base + (size_t)t * D_];
        float v = V[base + (size_t)t * D_];
        h = f * h + (1.f - f) * v;
        HS[base + (size_t)t * D_] = h;
    }
}

// ---------------- LayerNorm over last axis ----------------------------------
__global__ __launch_bounds__(256)
void ln_kernel(const float* __restrict__ Z, const float* __restrict__ g,
               const float* __restrict__ b, float* __restrict__ out)
{
    int row = blockIdx.x;
    int t = threadIdx.x;
    float4 x = reinterpret_cast<const float4*>(Z + (size_t)row * D_)[t];
    float s  = x.x + x.y + x.z + x.w;
    float ss = x.x * x.x + x.y * x.y + x.z * x.z + x.w * x.w;
#pragma unroll
    for (int o = 16; o > 0; o >>= 1) {
        s  += __shfl_xor_sync(0xFFFFFFFFu, s, o);
        ss += __shfl_xor_sync(0xFFFFFFFFu, ss, o);
    }
    __shared__ float sh_s[8], sh_ss[8];
    int w = t >> 5, l = t & 31;
    if (l == 0) { sh_s[w] = s; sh_ss[w] = ss; }
    __syncthreads();
    if (w == 0) {
        s  = (l < 8) ? sh_s[l]  : 0.f;
        ss = (l < 8) ? sh_ss[l] : 0.f;
#pragma unroll
        for (int o = 4; o > 0; o >>= 1) {
            s  += __shfl_xor_sync(0xFFFFFFFFu, s, o);
            ss += __shfl_xor_sync(0xFFFFFFFFu, ss, o);
        }
        if (l == 0) { sh_s[0] = s; sh_ss[0] = ss; }
    }
    __syncthreads();
    float mean = sh_s[0] * (1.f / D_);
    float var  = sh_ss[0] * (1.f / D_) - mean * mean;
    float rstd = rsqrtf(var + 1e-5f);
    float4 gg = reinterpret_cast<const float4*>(g)[t];
    float4 bb = reinterpret_cast<const float4*>(b)[t];
    float4 y;
    y.x = (x.x - mean) * rstd * gg.x + bb.x;
    y.y = (x.y - mean) * rstd * gg.y + bb.y;
    y.z = (x.z - mean) * rstd * gg.z + bb.z;
    y.w = (x.w - mean) * rstd * gg.w + bb.w;
    reinterpret_cast<float4*>(out + (size_t)row * D_)[t] = y;
}

// ---------------- launch -----------------------------------------------------
extern "C" void kernel_launch(void* const* d_in, const int* in_sizes, int n_in,
                              void* d_out, int out_size)
{
    const float* x         = (const float*)d_in[0];
    const float* hidden    = (const float*)d_in[1];
    const float* rnn_start = (const float*)d_in[2];
    const float* Win       = (const float*)d_in[3];
    const float* bin_      = (const float*)d_in[4];
    const float* Wout      = (const float*)d_in[5];
    const float* bout      = (const float*)d_in[6];
    const float* W1        = (const float*)d_in[7];
    const float* b1        = (const float*)d_in[8];
    const float* W2        = (const float*)d_in[9];
    const float* b2        = (const float*)d_in[10];
    const float* ln_g      = (const float*)d_in[11];
    const float* ln_b      = (const float*)d_in[12];

    float* out        = (float*)d_out;
    float* hidden_out = out + (size_t)M_ * D_;

    float *buf0, *buf1, *buf2, *wT;
    cudaGetSymbolAddress((void**)&buf0, g_buf0);
    cudaGetSymbolAddress((void**)&buf1, g_buf1);
    cudaGetSymbolAddress((void**)&buf2, g_buf2);
    cudaGetSymbolAddress((void**)&wT,   g_wT);

    cudaFuncSetAttribute(tgemm<MODE_TANH>,  cudaFuncAttributeMaxDynamicSharedMemorySize, GEMM_SMEM);
    cudaFuncSetAttribute(tgemm<MODE_SIGF>,  cudaFuncAttributeMaxDynamicSharedMemorySize, GEMM_SMEM);
    cudaFuncSetAttribute(tgemm<MODE_BIAS>,  cudaFuncAttributeMaxDynamicSharedMemorySize, GEMM_SMEM);
    cudaFuncSetAttribute(tgemm<MODE_GELU>,  cudaFuncAttributeMaxDynamicSharedMemorySize, GEMM_SMEM);
    cudaFuncSetAttribute(tgemm<MODE_RESID>, cudaFuncAttributeMaxDynamicSharedMemorySize, GEMM_SMEM);
    cudaFuncSetAttribute(scan_pass2, cudaFuncAttributeMaxDynamicSharedMemorySize, 2 * NC * 128 * 4);

    // transpose + tf32-round the 5 weight matrices: Win0, Win1, Wout, W1, W2
    transpose_tf32<<<dim3(32, 32, 5), dim3(32, 8)>>>(
        Win, Win + (size_t)K_ * D_, Wout, W1, W2, wT);

    dim3 grid(D_ / BNm, M_ / BMm);   // (8, 128)

    // v = tanh(x@Win0 + bin0) ; f = sigmoid(x@Win1 + bin1) * (1 - rnn_start)
    tgemm<MODE_TANH><<<grid, 256, GEMM_SMEM>>>(x, wT,                   bin_,      nullptr,   buf0);
    tgemm<MODE_SIGF><<<grid, 256, GEMM_SMEM>>>(x, wT + (size_t)K_ * D_, bin_ + D_, rnn_start, buf1);

    // chunked scan -> hs in buf2, hT -> hidden_out
    scan_pass1<<<(B_ * NC * D_) / 256, 256>>>(buf0, buf1);
    scan_pass2<<<32, 256, 2 * NC * 128 * 4>>>(hidden, hidden_out);
    scan_pass3<<<(B_ * NC * D_) / 256, 256>>>(buf0, buf1, buf2);

    // out = hs@Wout + bout ; x_ = gelu(out@W1+b1) ; z = x_@W2 + b2 + out ; LN
    tgemm<MODE_BIAS><<<grid, 256, GEMM_SMEM>>>(buf2, wT + 2 * (size_t)K_ * D_, bout, nullptr, buf0);
    tgemm<MODE_GELU><<<grid, 256, GEMM_SMEM>>>(buf0, wT + 3 * (size_t)K_ * D_, b1,   nullptr, buf1);
    tgemm<MODE_RESID><<<grid, 256, GEMM_SMEM>>>(buf1, wT + 4 * (size_t)K_ * D_, b2,  buf0,    buf2);
    ln_kernel<<<M_, 256>>>(buf2, ln_g, ln_b, out);
}

// round 4
// speedup vs baseline: 3.4692x; 1.0399x over previous
#include <cuda_runtime.h>
#include <math.h>
#include <stdint.h>

// Problem dims (fixed per setup_inputs)
#define B_   4
#define T_   4096
#define K_   1024          // Din == D == 1024
#define D_   1024
#define M_   (B_*T_)       // 16384

// ---------------- scratch (device globals; no allocations allowed) ---------
__device__ float g_buf0[(size_t)M_ * D_];   // 64 MB
__device__ float g_buf1[(size_t)M_ * D_];   // 64 MB
__device__ float g_buf2[(size_t)M_ * D_];   // 64 MB
__device__ float g_wT[(size_t)5 * K_ * D_]; // 20 MB transposed + tf32-rounded weights

#define CHUNK 32
#define NC    (T_/CHUNK)    // 128
__device__ float g_cA[B_*NC*D_];
__device__ float g_cP[B_*NC*D_];
__device__ float g_cC[B_*NC*D_];

// ---------------- helpers ----------------------------------------------------
__device__ __forceinline__ uint32_t cvt_tf32(float x) {
    uint32_t t; asm("cvt.rna.tf32.f32 %0, %1;" : "=r"(t) : "f"(x)); return t;
}
__device__ __forceinline__ uint32_t smem_u32(const void* p) {
    uint32_t a;
    asm("{ .reg .u64 t; cvta.to.shared.u64 t, %1; cvt.u32.u64 %0, t; }" : "=r"(a) : "l"(p));
    return a;
}
__device__ __forceinline__ void cp_async16(uint32_t saddr, const void* gptr) {
    asm volatile("cp.async.cg.shared.global [%0], [%1], 16;" :: "r"(saddr), "l"(gptr));
}
#define CP_COMMIT() asm volatile("cp.async.commit_group;" ::: "memory")
#define CP_WAIT1()  asm volatile("cp.async.wait_group 1;"  ::: "memory")

// ---------------- tf32 mma.sync GEMM: C[M,1024] = A[M,1024] @ Bt^T -----------
// A is PRE-ROUNDED to tf32 bits (stored as float). Bt is [N,K] tf32 bits.
// CTA tile 128x128, BK=32, 3-stage cp.async pipeline; 8 warps (2Mx4N), 64x32 each.

#define BMm 128
#define BNm 128
#define BKm 32
#define STEPSm (K_/BKm)        // 32
#define SROW  36               // padded row stride (words)
#define STAGE_WORDS (BMm*SROW) // 4608 words = 18432 B per matrix per stage
#define STAGE_B (STAGE_WORDS*4)
#define NSTG 3
#define GEMM_SMEM (2*NSTG*STAGE_B)   // 110592 B

enum { MODE_TANH = 0, MODE_SIGF = 1, MODE_BIAS = 2, MODE_GELU = 3, MODE_RESID = 4 };

__device__ __forceinline__ void mma_tf32(float c[4], const uint32_t a[4], const uint32_t b[2]) {
    asm volatile(
        "mma.sync.aligned.m16n8k8.row.col.f32.tf32.tf32.f32 "
        "{%0,%1,%2,%3}, {%4,%5,%6,%7}, {%8,%9}, {%0,%1,%2,%3};"
        : "+f"(c[0]), "+f"(c[1]), "+f"(c[2]), "+f"(c[3])
        : "r"(a[0]), "r"(a[1]), "r"(a[2]), "r"(a[3]), "r"(b[0]), "r"(b[1]));
}

template <int MODE>
__global__ __launch_bounds__(256, 2)
void tgemm(const float* __restrict__ A,       // [M,1024] tf32 bits
           const float* __restrict__ Bt,      // [1024,1024] tf32 bits, N-major
           const float* __restrict__ bias,    // [1024]
           const float* __restrict__ extra,   // rnn_start[M] (SIGF) or residual[M,1024] (RESID)
           float* __restrict__ C,             // [M,1024]
           float* __restrict__ C2)            // tf32 copy (MODE_BIAS only)
{
    extern __shared__ float sm[];
    const uint32_t sbase = smem_u32(sm);
    const uint32_t aB = sbase;
    const uint32_t bB = sbase + NSTG * STAGE_B;

    const int tid  = threadIdx.x;
    const int lane = tid & 31;
    const int wid  = tid >> 5;
    const int wm   = wid >> 2;          // 0..1
    const int wn   = wid & 3;           // 0..3
    const int bn   = blockIdx.x;        // 0..7
    const int bm   = blockIdx.y;        // 0..127

    const float* Ab = A  + (size_t)bm * BMm * K_;
    const float* Bb = Bt + (size_t)bn * BNm * K_;

    // per-thread cp.async mapping (4 x 16B per matrix per stage)
    const int r0 = tid >> 3;            // +32*j
    const int c4 = (tid & 7) << 2;
    const uint32_t soff0 = (uint32_t)(r0 * SROW + c4) * 4;

    float acc[4][4][4];
#pragma unroll
    for (int mi = 0; mi < 4; mi++)
#pragma unroll
        for (int ni = 0; ni < 4; ni++)
#pragma unroll
            for (int q = 0; q < 4; q++) acc[mi][ni][q] = 0.f;

    const int ar = wm * 64 + (lane >> 2);
    const int ak = lane & 3;
    const int br = wn * 32 + (lane >> 2);
    const int bk = lane & 3;

#define ISSUE_STAGE(S) do {                                                     \
        const int _k0 = (S) * BKm;                                              \
        const uint32_t _sa = aB + ((S) % NSTG) * STAGE_B + soff0;               \
        const uint32_t _sb = bB + ((S) % NSTG) * STAGE_B + soff0;               \
        _Pragma("unroll")                                                       \
        for (int j = 0; j < 4; j++) {                                           \
            const size_t go = (size_t)(r0 + 32 * j) * K_ + _k0 + c4;            \
            const uint32_t so = (uint32_t)(32 * j * SROW) * 4;                  \
            cp_async16(_sa + so, Ab + go);                                      \
            cp_async16(_sb + so, Bb + go);                                      \
        }                                                                       \
    } while (0)

    ISSUE_STAGE(0); CP_COMMIT();
    ISSUE_STAGE(1); CP_COMMIT();

    for (int s = 0; s < STEPSm; s++) {
        CP_WAIT1();
        __syncthreads();
        if (s + 2 < STEPSm) { ISSUE_STAGE(s + 2); CP_COMMIT(); }

        const uint32_t* cA = reinterpret_cast<const uint32_t*>(sm) + (s % NSTG) * STAGE_WORDS;
        const uint32_t* cB = reinterpret_cast<const uint32_t*>(sm) + NSTG * STAGE_WORDS
                             + (s % NSTG) * STAGE_WORDS;
#pragma unroll
        for (int ks = 0; ks < 4; ks++) {
            const int k0 = ks * 8;
            uint32_t afr[4][4];
#pragma unroll
            for (int mi = 0; mi < 4; mi++) {
                const uint32_t* p = cA + (ar + mi * 16) * SROW + k0 + ak;
                afr[mi][0] = p[0];
                afr[mi][1] = p[8 * SROW];
                afr[mi][2] = p[4];
                afr[mi][3] = p[8 * SROW + 4];
            }
            uint32_t bfr[4][2];
#pragma unroll
            for (int ni = 0; ni < 4; ni++) {
                const uint32_t* p = cB + (br + ni * 8) * SROW + k0 + bk;
                bfr[ni][0] = p[0];
                bfr[ni][1] = p[4];
            }
#pragma unroll
            for (int mi = 0; mi < 4; mi++)
#pragma unroll
                for (int ni = 0; ni < 4; ni++)
                    mma_tf32(acc[mi][ni], afr[mi], bfr[ni]);
        }
    }
#undef ISSUE_STAGE

    // ---- fused epilogue
    const int r_base = bm * BMm + wm * 64 + (lane >> 2);
    const int c_base = bn * BNm + wn * 32 + ((lane & 3) << 1);
#pragma unroll
    for (int mi = 0; mi < 4; mi++) {
        const int gr0 = r_base + mi * 16;
        const int gr1 = gr0 + 8;
        float rs0 = 0.f, rs1 = 0.f;
        if (MODE == MODE_SIGF) { rs0 = extra[gr0]; rs1 = extra[gr1]; }
#pragma unroll
        for (int ni = 0; ni < 4; ni++) {
            const int gc = c_base + ni * 8;
            float b0 = bias[gc], b1 = bias[gc + 1];
            float v0 = acc[mi][ni][0] + b0;
            float v1 = acc[mi][ni][1] + b1;
            float v2 = acc[mi][ni][2] + b0;
            float v3 = acc[mi][ni][3] + b1;
            if (MODE == MODE_TANH) {
                v0 = tanhf(v0); v1 = tanhf(v1); v2 = tanhf(v2); v3 = tanhf(v3);
            } else if (MODE == MODE_SIGF) {
                v0 = (1.f - rs0) / (1.f + expf(-v0));
                v1 = (1.f - rs0) / (1.f + expf(-v1));
                v2 = (1.f - rs1) / (1.f + expf(-v2));
                v3 = (1.f - rs1) / (1.f + expf(-v3));
            } else if (MODE == MODE_GELU) {
                v0 = 0.5f * v0 * (1.f + erff(v0 * 0.70710678118654752f));
                v1 = 0.5f * v1 * (1.f + erff(v1 * 0.70710678118654752f));
                v2 = 0.5f * v2 * (1.f + erff(v2 * 0.70710678118654752f));
                v3 = 0.5f * v3 * (1.f + erff(v3 * 0.70710678118654752f));
                // output feeds next GEMM's A only: store tf32-rounded bits
                v0 = __uint_as_float(cvt_tf32(v0));
                v1 = __uint_as_float(cvt_tf32(v1));
                v2 = __uint_as_float(cvt_tf32(v2));
                v3 = __uint_as_float(cvt_tf32(v3));
            } else if (MODE == MODE_RESID) {
                const float2 e0 = *reinterpret_cast<const float2*>(extra + (size_t)gr0 * D_ + gc);
                const float2 e1 = *reinterpret_cast<const float2*>(extra + (size_t)gr1 * D_ + gc);
                v0 += e0.x; v1 += e0.y; v2 += e1.x; v3 += e1.y;
            }
            *reinterpret_cast<float2*>(C + (size_t)gr0 * D_ + gc) = make_float2(v0, v1);
            *reinterpret_cast<float2*>(C + (size_t)gr1 * D_ + gc) = make_float2(v2, v3);
            if (MODE == MODE_BIAS) {   // extra tf32 copy for next GEMM's A
                float t0 = __uint_as_float(cvt_tf32(v0));
                float t1 = __uint_as_float(cvt_tf32(v1));
                float t2 = __uint_as_float(cvt_tf32(v2));
                float t3 = __uint_as_float(cvt_tf32(v3));
                *reinterpret_cast<float2*>(C2 + (size_t)gr0 * D_ + gc) = make_float2(t0, t1);
                *reinterpret_cast<float2*>(C2 + (size_t)gr1 * D_ + gc) = make_float2(t2, t3);
            }
        }
    }
}

// ---------------- x -> tf32-rounded copy ------------------------------------
__global__ void cvt_x_kernel(const float* __restrict__ x, float* __restrict__ xt)
{
    int i = blockIdx.x * blockDim.x + threadIdx.x;
    float4 v = reinterpret_cast<const float4*>(x)[i];
    float4 o;
    o.x = __uint_as_float(cvt_tf32(v.x));
    o.y = __uint_as_float(cvt_tf32(v.y));
    o.z = __uint_as_float(cvt_tf32(v.z));
    o.w = __uint_as_float(cvt_tf32(v.w));
    reinterpret_cast<float4*>(xt)[i] = o;
}

// ---------------- weight transpose + tf32 rounding --------------------------
__global__ void transpose_tf32(const float* __restrict__ s0, const float* __restrict__ s1,
                               const float* __restrict__ s2, const float* __restrict__ s3,
                               const float* __restrict__ s4, float* __restrict__ dst)
{
    __shared__ float tile[32][33];
    const int z = blockIdx.z;
    const float* src = (z == 0) ? s0 : (z == 1) ? s1 : (z == 2) ? s2 : (z == 3) ? s3 : s4;
    float* d = dst + (size_t)z * K_ * D_;
    const int n0 = blockIdx.x * 32, k0 = blockIdx.y * 32;
    const int tx = threadIdx.x, ty = threadIdx.y;   // 32x8
#pragma unroll
    for (int r = 0; r < 32; r += 8)
        tile[ty + r][tx] = src[(size_t)(k0 + ty + r) * D_ + n0 + tx];
    __syncthreads();
#pragma unroll
    for (int r = 0; r < 32; r += 8) {
        uint32_t t = cvt_tf32(tile[tx][ty + r]);
        d[(size_t)(n0 + ty + r) * K_ + k0 + tx] = __uint_as_float(t);
    }
}

// ---------------- chunked scan: h_t = f_t*h_{t-1} + (1-f_t)*v_t -------------
__global__ void scan_pass1(const float* __restrict__ V, const float* __restrict__ F)
{
    int idx = blockIdx.x * blockDim.x + threadIdx.x;
    int d = idx % D_;
    int c = (idx / D_) % NC;
    int b = idx / (D_ * NC);
    size_t base = ((size_t)b * T_ + (size_t)c * CHUNK) * D_ + d;
    float A = 1.f, h = 0.f;
#pragma unroll 8
    for (int t = 0; t < CHUNK; t++) {
        float f = F[base + (size_t)t * D_];
        float v = V[base + (size_t)t * D_];
        A *= f;
        h = f * h + (1.f - f) * v;
    }
    g_cA[idx] = A;
    g_cP[idx] = h;
}

__global__ void scan_pass2(const float* __restrict__ hidden, float* __restrict__ hT_out)
{
    extern __shared__ float sh[];          // sA[128*128], sP[128*128]
    float* sA = sh;
    float* sP = sh + NC * 128;
    const int blk = blockIdx.x;
    const int b   = blk >> 3;
    const int d0  = (blk & 7) * 128;
#pragma unroll 4
    for (int j = 0; j < 64; j++) {
        int i  = threadIdx.x + 256 * j;
        int c  = i >> 7, dd = i & 127;
        size_t g = ((size_t)b * NC + c) * D_ + d0 + dd;
        sA[i] = g_cA[g];
        sP[i] = g_cP[g];
    }
    __syncthreads();
    if (threadIdx.x < 128) {
        const int dd = threadIdx.x;
        float h = hidden[(size_t)b * D_ + d0 + dd];
        for (int c = 0; c < NC; c++) {
            g_cC[((size_t)b * NC + c) * D_ + d0 + dd] = h;
            h = sA[c * 128 + dd] * h + sP[c * 128 + dd];
        }
        hT_out[(size_t)b * D_ + d0 + dd] = h;
    }
}

// emits hs pre-rounded to tf32 (consumed only as GEMM3's A operand)
__global__ void scan_pass3(const float* __restrict__ V, const float* __restrict__ F,
                           float* __restrict__ HS)
{
    int idx = blockIdx.x * blockDim.x + threadIdx.x;
    int d = idx % D_;
    int c = (idx / D_) % NC;
    int b = idx / (D_ * NC);
    size_t base = ((size_t)b * T_ + (size_t)c * CHUNK) * D_ + d;
    float h = g_cC[idx];
#pragma unroll 8
    for (int t = 0; t < CHUNK; t++) {
        float f = F[base + (size_t)t * D_];
        float v = V[base + (size_t)t * D_];
        h = f * h + (1.f - f) * v;
        HS[base + (size_t)t * D_] = __uint_as_float(cvt_tf32(h));
    }
}

// ---------------- LayerNorm over last axis ----------------------------------
__global__ __launch_bounds__(256)
void ln_kernel(const float* __restrict__ Z, const float* __restrict__ g,
               const float* __restrict__ b, float* __restrict__ out)
{
    int row = blockIdx.x;
    int t = threadIdx.x;
    float4 x = reinterpret_cast<const float4*>(Z + (size_t)row * D_)[t];
    float s  = x.x + x.y + x.z + x.w;
    float ss = x.x * x.x + x.y * x.y + x.z * x.z + x.w * x.w;
#pragma unroll
    for (int o = 16; o > 0; o >>= 1) {
        s  += __shfl_xor_sync(0xFFFFFFFFu, s, o);
        ss += __shfl_xor_sync(0xFFFFFFFFu, ss, o);
    }
    __shared__ float sh_s[8], sh_ss[8];
    int w = t >> 5, l = t & 31;
    if (l == 0) { sh_s[w] = s; sh_ss[w] = ss; }
    __syncthreads();
    if (w == 0) {
        s  = (l < 8) ? sh_s[l]  : 0.f;
        ss = (l < 8) ? sh_ss[l] : 0.f;
#pragma unroll
        for (int o = 4; o > 0; o >>= 1) {
            s  += __shfl_xor_sync(0xFFFFFFFFu, s, o);
            ss += __shfl_xor_sync(0xFFFFFFFFu, ss, o);
        }
        if (l == 0) { sh_s[0] = s; sh_ss[0] = ss; }
    }
    __syncthreads();
    float mean = sh_s[0] * (1.f / D_);
    float var  = sh_ss[0] * (1.f / D_) - mean * mean;
    float rstd = rsqrtf(var + 1e-5f);
    float4 gg = reinterpret_cast<const float4*>(g)[t];
    float4 bb = reinterpret_cast<const float4*>(b)[t];
    float4 y;
    y.x = (x.x - mean) * rstd * gg.x + bb.x;
    y.y = (x.y - mean) * rstd * gg.y + bb.y;
    y.z = (x.z - mean) * rstd * gg.z + bb.z;
    y.w = (x.w - mean) * rstd * gg.w + bb.w;
    reinterpret_cast<float4*>(out + (size_t)row * D_)[t] = y;
}

// ---------------- launch -----------------------------------------------------
extern "C" void kernel_launch(void* const* d_in, const int* in_sizes, int n_in,
                              void* d_out, int out_size)
{
    const float* x         = (const float*)d_in[0];
    const float* hidden    = (const float*)d_in[1];
    const float* rnn_start = (const float*)d_in[2];
    const float* Win       = (const float*)d_in[3];
    const float* bin_      = (const float*)d_in[4];
    const float* Wout      = (const float*)d_in[5];
    const float* bout      = (const float*)d_in[6];
    const float* W1        = (const float*)d_in[7];
    const float* b1        = (const float*)d_in[8];
    const float* W2        = (const float*)d_in[9];
    const float* b2        = (const float*)d_in[10];
    const float* ln_g      = (const float*)d_in[11];
    const float* ln_b      = (const float*)d_in[12];

    float* out        = (float*)d_out;
    float* hidden_out = out + (size_t)M_ * D_;

    float *buf0, *buf1, *buf2, *wT;
    cudaGetSymbolAddress((void**)&buf0, g_buf0);
    cudaGetSymbolAddress((void**)&buf1, g_buf1);
    cudaGetSymbolAddress((void**)&buf2, g_buf2);
    cudaGetSymbolAddress((void**)&wT,   g_wT);

    cudaFuncSetAttribute(tgemm<MODE_TANH>,  cudaFuncAttributeMaxDynamicSharedMemorySize, GEMM_SMEM);
    cudaFuncSetAttribute(tgemm<MODE_SIGF>,  cudaFuncAttributeMaxDynamicSharedMemorySize, GEMM_SMEM);
    cudaFuncSetAttribute(tgemm<MODE_BIAS>,  cudaFuncAttributeMaxDynamicSharedMemorySize, GEMM_SMEM);
    cudaFuncSetAttribute(tgemm<MODE_GELU>,  cudaFuncAttributeMaxDynamicSharedMemorySize, GEMM_SMEM);
    cudaFuncSetAttribute(tgemm<MODE_RESID>, cudaFuncAttributeMaxDynamicSharedMemorySize, GEMM_SMEM);
    cudaFuncSetAttribute(scan_pass2, cudaFuncAttributeMaxDynamicSharedMemorySize, 2 * NC * 128 * 4);

    // weight transpose + tf32 round; x -> tf32 copy (buf2 is free until pass3)
    transpose_tf32<<<dim3(32, 32, 5), dim3(32, 8)>>>(
        Win, Win + (size_t)K_ * D_, Wout, W1, W2, wT);
    cvt_x_kernel<<<(M_ * K_) / (256 * 4), 256>>>(x, buf2);

    dim3 grid(D_ / BNm, M_ / BMm);   // (8, 128)

    // v = tanh(xt@Win0 + bin0) -> buf0 ; f = sigmoid(xt@Win1 + bin1)*(1-rs) -> buf1
    tgemm<MODE_TANH><<<grid, 256, GEMM_SMEM>>>(buf2, wT,                   bin_,      nullptr,   buf0, nullptr);
    tgemm<MODE_SIGF><<<grid, 256, GEMM_SMEM>>>(buf2, wT + (size_t)K_ * D_, bin_ + D_, rnn_start, buf1, nullptr);

    // chunked scan -> hs (tf32 bits) in buf2, hT -> hidden_out
    scan_pass1<<<(B_ * NC * D_) / 256, 256>>>(buf0, buf1);
    scan_pass2<<<32, 256, 2 * NC * 128 * 4>>>(hidden, hidden_out);
    scan_pass3<<<(B_ * NC * D_) / 256, 256>>>(buf0, buf1, buf2);

    // out = hs@Wout + bout -> buf0 (fp32) + buf1 (tf32 copy)
    tgemm<MODE_BIAS><<<grid, 256, GEMM_SMEM>>>(buf2, wT + 2 * (size_t)K_ * D_, bout, nullptr, buf0, buf1);
    // x_ = gelu(out@W1 + b1) -> buf2 (tf32 bits)
    tgemm<MODE_GELU><<<grid, 256, GEMM_SMEM>>>(buf1, wT + 3 * (size_t)K_ * D_, b1,   nullptr, buf2, nullptr);
    // z = x_@W2 + b2 + out -> buf1 (fp32)
    tgemm<MODE_RESID><<<grid, 256, GEMM_SMEM>>>(buf2, wT + 4 * (size_t)K_ * D_, b2,  buf0,    buf1, nullptr);
    // out = LN(z)
    ln_kernel<<<M_, 256>>>(buf1, ln_g, ln_b, out);
}

// round 5
// speedup vs baseline: 3.7416x; 1.0785x over previous
#include <cuda_runtime.h>
#include <math.h>
#include <stdint.h>

// Problem dims (fixed per setup_inputs)
#define B_   4
#define T_   4096
#define K_   1024          // Din == D == 1024
#define D_   1024
#define M_   (B_*T_)       // 16384

// ---------------- scratch (device globals; no allocations allowed) ---------
__device__ float g_buf0[(size_t)M_ * D_];   // 64 MB
__device__ float g_buf1[(size_t)M_ * D_];   // 64 MB
__device__ float g_buf2[(size_t)M_ * D_];   // 64 MB
__device__ float g_wT[(size_t)5 * K_ * D_]; // 20 MB transposed + tf32-rounded weights

#define CHUNK 32
#define NC    (T_/CHUNK)    // 128
__device__ float g_cA[B_*NC*D_];
__device__ float g_cP[B_*NC*D_];
__device__ float g_cC[B_*NC*D_];

// ---------------- helpers ----------------------------------------------------
__device__ __forceinline__ uint32_t cvt_tf32(float x) {
    uint32_t t; asm("cvt.rna.tf32.f32 %0, %1;" : "=r"(t) : "f"(x)); return t;
}
__device__ __forceinline__ uint32_t smem_u32(const void* p) {
    uint32_t a;
    asm("{ .reg .u64 t; cvta.to.shared.u64 t, %1; cvt.u32.u64 %0, t; }" : "=r"(a) : "l"(p));
    return a;
}
__device__ __forceinline__ void cp_async16(uint32_t saddr, const void* gptr) {
    asm volatile("cp.async.cg.shared.global [%0], [%1], 16;" :: "r"(saddr), "l"(gptr));
}
#define CP_COMMIT() asm volatile("cp.async.commit_group;" ::: "memory")
#define CP_WAIT1()  asm volatile("cp.async.wait_group 1;"  ::: "memory")

#define LDSM_X4(r0, r1, r2, r3, addr) \
    asm volatile("ldmatrix.sync.aligned.m8n8.x4.shared.b16 {%0,%1,%2,%3}, [%4];" \
                 : "=r"(r0), "=r"(r1), "=r"(r2), "=r"(r3) : "r"(addr))

__device__ __forceinline__ void mma_tf32(float c[4], const uint32_t a[4], const uint32_t b[2]) {
    asm volatile(
        "mma.sync.aligned.m16n8k8.row.col.f32.tf32.tf32.f32 "
        "{%0,%1,%2,%3}, {%4,%5,%6,%7}, {%8,%9}, {%0,%1,%2,%3};"
        : "+f"(c[0]), "+f"(c[1]), "+f"(c[2]), "+f"(c[3])
        : "r"(a[0]), "r"(a[1]), "r"(a[2]), "r"(a[3]), "r"(b[0]), "r"(b[1]));
}

// ---------------- tf32 mma.sync GEMM core ------------------------------------
// A [M,1024] tf32 bits; Bt [N,K] tf32 bits (N-major). CTA 128x128, BK=32,
// 3-stage cp.async; 8 warps (2M x 4N), warp 64x32; LDSM fragment loads.

#define BMm 128
#define BNm 128
#define BKm 32
#define STEPSm (K_/BKm)        // 32
#define SROW  36               // padded row stride (words)
#define STAGE_WORDS (BMm*SROW)
#define STAGE_B (STAGE_WORDS*4)
#define NSTG 3
#define GEMM_SMEM (2*NSTG*STAGE_B)   // 110592 B

enum { MODE_TANH = 0, MODE_SIGF = 1, MODE_BIAS = 2, MODE_GELU = 3, MODE_RESID = 4 };

struct Frag { float acc[4][4][4]; };

__device__ __forceinline__ void gemm_mainloop(
    const float* __restrict__ Ab, const float* __restrict__ Bb,
    uint32_t sbase, int tid, int lane, int wm, int wn, Frag& fr)
{
    const uint32_t aB = sbase;
    const uint32_t bB = sbase + NSTG * STAGE_B;

    // cp.async mapping: 4 x 16B per matrix per stage per thread
    const int r0 = tid >> 3;
    const int c4 = (tid & 7) << 2;
    const uint32_t soff0 = (uint32_t)(r0 * SROW + c4) * 4;

    // LDSM per-lane offsets (bytes within a stage)
    const int rr = lane & 7;
    const int a_row8  = (lane >> 3) & 1;
    const int a_khalf = (lane >> 4) & 1;
    uint32_t aoff[4];
#pragma unroll
    for (int mi = 0; mi < 4; mi++)
        aoff[mi] = (uint32_t)((wm * 64 + mi * 16 + a_row8 * 8 + rr) * SROW + a_khalf * 4) * 4;
    const int b_khalf = (lane >> 3) & 1;
    const int b_n8    = (lane >> 4) & 1;
    uint32_t boff[2];
#pragma unroll
    for (int j = 0; j < 2; j++)
        boff[j] = (uint32_t)((wn * 32 + j * 16 + b_n8 * 8 + rr) * SROW + b_khalf * 4) * 4;

#pragma unroll
    for (int mi = 0; mi < 4; mi++)
#pragma unroll
        for (int ni = 0; ni < 4; ni++)
#pragma unroll
            for (int q = 0; q < 4; q++) fr.acc[mi][ni][q] = 0.f;

#define ISSUE_STAGE(S) do {                                                     \
        const int _k0 = (S) * BKm;                                              \
        const uint32_t _sa = aB + ((S) % NSTG) * STAGE_B + soff0;               \
        const uint32_t _sb = bB + ((S) % NSTG) * STAGE_B + soff0;               \
        _Pragma("unroll")                                                       \
        for (int j = 0; j < 4; j++) {                                           \
            const size_t go = (size_t)(r0 + 32 * j) * K_ + _k0 + c4;            \
            const uint32_t so = (uint32_t)(32 * j * SROW) * 4;                  \
            cp_async16(_sa + so, Ab + go);                                      \
            cp_async16(_sb + so, Bb + go);                                      \
        }                                                                       \
    } while (0)

    ISSUE_STAGE(0); CP_COMMIT();
    ISSUE_STAGE(1); CP_COMMIT();

    for (int s = 0; s < STEPSm; s++) {
        CP_WAIT1();
        __syncthreads();
        if (s + 2 < STEPSm) { ISSUE_STAGE(s + 2); CP_COMMIT(); }

        const uint32_t sa = aB + (s % NSTG) * STAGE_B;
        const uint32_t sb = bB + (s % NSTG) * STAGE_B;
#pragma unroll
        for (int ks = 0; ks < 4; ks++) {
            const uint32_t ko = (uint32_t)ks * 32;   // 8 words
            uint32_t af[4][4];
#pragma unroll
            for (int mi = 0; mi < 4; mi++)
                LDSM_X4(af[mi][0], af[mi][1], af[mi][2], af[mi][3], sa + aoff[mi] + ko);
            uint32_t bq[2][4];
#pragma unroll
            for (int j = 0; j < 2; j++)
                LDSM_X4(bq[j][0], bq[j][1], bq[j][2], bq[j][3], sb + boff[j] + ko);
#pragma unroll
            for (int mi = 0; mi < 4; mi++)
#pragma unroll
                for (int ni = 0; ni < 4; ni++) {
                    const uint32_t bfr[2] = { bq[ni >> 1][(ni & 1) * 2],
                                              bq[ni >> 1][(ni & 1) * 2 + 1] };
                    mma_tf32(fr.acc[mi][ni], af[mi], bfr);
                }
        }
    }
#undef ISSUE_STAGE
}

// ---- chain GEMMs (BIAS / GELU / RESID) --------------------------------------
template <int MODE>
__global__ __launch_bounds__(256, 2)
void tgemm(const float* __restrict__ A, const float* __restrict__ Bt,
           const float* __restrict__ bias, const float* __restrict__ extra,
           float* __restrict__ C, float* __restrict__ C2)
{
    extern __shared__ float smf[];
    const uint32_t sbase = smem_u32(smf);
    const int tid = threadIdx.x, lane = tid & 31, wid = tid >> 5;
    const int wm = wid >> 2, wn = wid & 3;
    const int bn = blockIdx.x, bm = blockIdx.y;

    Frag fr;
    gemm_mainloop(A + (size_t)bm * BMm * K_, Bt + (size_t)bn * BNm * K_,
                  sbase, tid, lane, wm, wn, fr);

    const int r_base = bm * BMm + wm * 64 + (lane >> 2);
    const int c_base = bn * BNm + wn * 32 + ((lane & 3) << 1);
#pragma unroll
    for (int mi = 0; mi < 4; mi++) {
        const int gr0 = r_base + mi * 16;
        const int gr1 = gr0 + 8;
#pragma unroll
        for (int ni = 0; ni < 4; ni++) {
            const int gc = c_base + ni * 8;
            float b0 = bias[gc], b1 = bias[gc + 1];
            float v0 = fr.acc[mi][ni][0] + b0;
            float v1 = fr.acc[mi][ni][1] + b1;
            float v2 = fr.acc[mi][ni][2] + b0;
            float v3 = fr.acc[mi][ni][3] + b1;
            if (MODE == MODE_GELU) {
                v0 = 0.5f * v0 * (1.f + erff(v0 * 0.70710678118654752f));
                v1 = 0.5f * v1 * (1.f + erff(v1 * 0.70710678118654752f));
                v2 = 0.5f * v2 * (1.f + erff(v2 * 0.70710678118654752f));
                v3 = 0.5f * v3 * (1.f + erff(v3 * 0.70710678118654752f));
                v0 = __uint_as_float(cvt_tf32(v0));
                v1 = __uint_as_float(cvt_tf32(v1));
                v2 = __uint_as_float(cvt_tf32(v2));
                v3 = __uint_as_float(cvt_tf32(v3));
            } else if (MODE == MODE_RESID) {
                const float2 e0 = *reinterpret_cast<const float2*>(extra + (size_t)gr0 * D_ + gc);
                const float2 e1 = *reinterpret_cast<const float2*>(extra + (size_t)gr1 * D_ + gc);
                v0 += e0.x; v1 += e0.y; v2 += e1.x; v3 += e1.y;
            }
            *reinterpret_cast<float2*>(C + (size_t)gr0 * D_ + gc) = make_float2(v0, v1);
            *reinterpret_cast<float2*>(C + (size_t)gr1 * D_ + gc) = make_float2(v2, v3);
            if (MODE == MODE_BIAS) {
                float t0 = __uint_as_float(cvt_tf32(v0));
                float t1 = __uint_as_float(cvt_tf32(v1));
                float t2 = __uint_as_float(cvt_tf32(v2));
                float t3 = __uint_as_float(cvt_tf32(v3));
                *reinterpret_cast<float2*>(C2 + (size_t)gr0 * D_ + gc) = make_float2(t0, t1);
                *reinterpret_cast<float2*>(C2 + (size_t)gr1 * D_ + gc) = make_float2(t2, t3);
            }
        }
    }
}

// ---- fused gate GEMMs: z=0 -> tanh -> Cv ; z=1 -> sigmoid*(1-rs) -> Cf ------
__global__ __launch_bounds__(256, 2)
void tgemm_gates(const float* __restrict__ A, const float* __restrict__ Wt,
                 const float* __restrict__ bin, const float* __restrict__ rnn_start,
                 float* __restrict__ Cv, float* __restrict__ Cf)
{
    extern __shared__ float smf[];
    const uint32_t sbase = smem_u32(smf);
    const int tid = threadIdx.x, lane = tid & 31, wid = tid >> 5;
    const int wm = wid >> 2, wn = wid & 3;
    const int bn = blockIdx.x, bm = blockIdx.y, z = blockIdx.z;

    const float* Bt   = Wt + (size_t)z * K_ * D_;
    const float* bias = bin + z * D_;

    Frag fr;
    gemm_mainloop(A + (size_t)bm * BMm * K_, Bt + (size_t)bn * BNm * K_,
                  sbase, tid, lane, wm, wn, fr);

    float* C = z ? Cf : Cv;
    const int r_base = bm * BMm + wm * 64 + (lane >> 2);
    const int c_base = bn * BNm + wn * 32 + ((lane & 3) << 1);
#pragma unroll
    for (int mi = 0; mi < 4; mi++) {
        const int gr0 = r_base + mi * 16;
        const int gr1 = gr0 + 8;
        float rs0 = 0.f, rs1 = 0.f;
        if (z) { rs0 = rnn_start[gr0]; rs1 = rnn_start[gr1]; }
#pragma unroll
        for (int ni = 0; ni < 4; ni++) {
            const int gc = c_base + ni * 8;
            float b0 = bias[gc], b1 = bias[gc + 1];
            float v0 = fr.acc[mi][ni][0] + b0;
            float v1 = fr.acc[mi][ni][1] + b1;
            float v2 = fr.acc[mi][ni][2] + b0;
            float v3 = fr.acc[mi][ni][3] + b1;
            if (z == 0) {
                v0 = tanhf(v0); v1 = tanhf(v1); v2 = tanhf(v2); v3 = tanhf(v3);
            } else {
                v0 = (1.f - rs0) / (1.f + expf(-v0));
                v1 = (1.f - rs0) / (1.f + expf(-v1));
                v2 = (1.f - rs1) / (1.f + expf(-v2));
                v3 = (1.f - rs1) / (1.f + expf(-v3));
            }
            *reinterpret_cast<float2*>(C + (size_t)gr0 * D_ + gc) = make_float2(v0, v1);
            *reinterpret_cast<float2*>(C + (size_t)gr1 * D_ + gc) = make_float2(v2, v3);
        }
    }
}

// ---------------- x -> tf32-rounded copy ------------------------------------
__global__ void cvt_x_kernel(const float* __restrict__ x, float* __restrict__ xt)
{
    int i = blockIdx.x * blockDim.x + threadIdx.x;
    float4 v = reinterpret_cast<const float4*>(x)[i];
    float4 o;
    o.x = __uint_as_float(cvt_tf32(v.x));
    o.y = __uint_as_float(cvt_tf32(v.y));
    o.z = __uint_as_float(cvt_tf32(v.z));
    o.w = __uint_as_float(cvt_tf32(v.w));
    reinterpret_cast<float4*>(xt)[i] = o;
}

// ---------------- weight transpose + tf32 rounding --------------------------
__global__ void transpose_tf32(const float* __restrict__ s0, const float* __restrict__ s1,
                               const float* __restrict__ s2, const float* __restrict__ s3,
                               const float* __restrict__ s4, float* __restrict__ dst)
{
    __shared__ float tile[32][33];
    const int z = blockIdx.z;
    const float* src = (z == 0) ? s0 : (z == 1) ? s1 : (z == 2) ? s2 : (z == 3) ? s3 : s4;
    float* d = dst + (size_t)z * K_ * D_;
    const int n0 = blockIdx.x * 32, k0 = blockIdx.y * 32;
    const int tx = threadIdx.x, ty = threadIdx.y;
#pragma unroll
    for (int r = 0; r < 32; r += 8)
        tile[ty + r][tx] = src[(size_t)(k0 + ty + r) * D_ + n0 + tx];
    __syncthreads();
#pragma unroll
    for (int r = 0; r < 32; r += 8) {
        uint32_t t = cvt_tf32(tile[tx][ty + r]);
        d[(size_t)(n0 + ty + r) * K_ + k0 + tx] = __uint_as_float(t);
    }
}

// ---------------- chunked scan ----------------------------------------------
__global__ void scan_pass1(const float* __restrict__ V, const float* __restrict__ F)
{
    int idx = blockIdx.x * blockDim.x + threadIdx.x;
    int d = idx % D_;
    int c = (idx / D_) % NC;
    int b = idx / (D_ * NC);
    size_t base = ((size_t)b * T_ + (size_t)c * CHUNK) * D_ + d;
    float A = 1.f, h = 0.f;
#pragma unroll 8
    for (int t = 0; t < CHUNK; t++) {
        float f = F[base + (size_t)t * D_];
        float v = V[base + (size_t)t * D_];
        A *= f;
        h = f * h + (1.f - f) * v;
    }
    g_cA[idx] = A;
    g_cP[idx] = h;
}

__global__ void scan_pass2(const float* __restrict__ hidden, float* __restrict__ hT_out)
{
    extern __shared__ float sh[];
    float* sA = sh;
    float* sP = sh + NC * 128;
    const int blk = blockIdx.x;
    const int b   = blk >> 3;
    const int d0  = (blk & 7) * 128;
#pragma unroll 4
    for (int j = 0; j < 64; j++) {
        int i  = threadIdx.x + 256 * j;
        int c  = i >> 7, dd = i & 127;
        size_t g = ((size_t)b * NC + c) * D_ + d0 + dd;
        sA[i] = g_cA[g];
        sP[i] = g_cP[g];
    }
    __syncthreads();
    if (threadIdx.x < 128) {
        const int dd = threadIdx.x;
        float h = hidden[(size_t)b * D_ + d0 + dd];
        for (int c = 0; c < NC; c++) {
            g_cC[((size_t)b * NC + c) * D_ + d0 + dd] = h;
            h = sA[c * 128 + dd] * h + sP[c * 128 + dd];
        }
        hT_out[(size_t)b * D_ + d0 + dd] = h;
    }
}

__global__ void scan_pass3(const float* __restrict__ V, const float* __restrict__ F,
                           float* __restrict__ HS)
{
    int idx = blockIdx.x * blockDim.x + threadIdx.x;
    int d = idx % D_;
    int c = (idx / D_) % NC;
    int b = idx / (D_ * NC);
    size_t base = ((size_t)b * T_ + (size_t)c * CHUNK) * D_ + d;
    float h = g_cC[idx];
#pragma unroll 8
    for (int t = 0; t < CHUNK; t++) {
        float f = F[base + (size_t)t * D_];
        float v = V[base + (size_t)t * D_];
        h = f * h + (1.f - f) * v;
        HS[base + (size_t)t * D_] = __uint_as_float(cvt_tf32(h));
    }
}

// ---------------- LayerNorm ---------------------------------------------------
__global__ __launch_bounds__(256)
void ln_kernel(const float* __restrict__ Z, const float* __restrict__ g,
               const float* __restrict__ b, float* __restrict__ out)
{
    int row = blockIdx.x;
    int t = threadIdx.x;
    float4 x = reinterpret_cast<const float4*>(Z + (size_t)row * D_)[t];
    float s  = x.x + x.y + x.z + x.w;
    float ss = x.x * x.x + x.y * x.y + x.z * x.z + x.w * x.w;
#pragma unroll
    for (int o = 16; o > 0; o >>= 1) {
        s  += __shfl_xor_sync(0xFFFFFFFFu, s, o);
        ss += __shfl_xor_sync(0xFFFFFFFFu, ss, o);
    }
    __shared__ float sh_s[8], sh_ss[8];
    int w = t >> 5, l = t & 31;
    if (l == 0) { sh_s[w] = s; sh_ss[w] = ss; }
    __syncthreads();
    if (w == 0) {
        s  = (l < 8) ? sh_s[l]  : 0.f;
        ss = (l < 8) ? sh_ss[l] : 0.f;
#pragma unroll
        for (int o = 4; o > 0; o >>= 1) {
            s  += __shfl_xor_sync(0xFFFFFFFFu, s, o);
            ss += __shfl_xor_sync(0xFFFFFFFFu, ss, o);
        }
        if (l == 0) { sh_s[0] = s; sh_ss[0] = ss; }
    }
    __syncthreads();
    float mean = sh_s[0] * (1.f / D_);
    float var  = sh_ss[0] * (1.f / D_) - mean * mean;
    float rstd = rsqrtf(var + 1e-5f);
    float4 gg = reinterpret_cast<const float4*>(g)[t];
    float4 bb = reinterpret_cast<const float4*>(b)[t];
    float4 y;
    y.x = (x.x - mean) * rstd * gg.x + bb.x;
    y.y = (x.y - mean) * rstd * gg.y + bb.y;
    y.z = (x.z - mean) * rstd * gg.z + bb.z;
    y.w = (x.w - mean) * rstd * gg.w + bb.w;
    reinterpret_cast<float4*>(out + (size_t)row * D_)[t] = y;
}

// ---------------- launch -------------------------------------------------------
extern "C" void kernel_launch(void* const* d_in, const int* in_sizes, int n_in,
                              void* d_out, int out_size)
{
    const float* x         = (const float*)d_in[0];
    const float* hidden    = (const float*)d_in[1];
    const float* rnn_start = (const float*)d_in[2];
    const float* Win       = (const float*)d_in[3];
    const float* bin_      = (const float*)d_in[4];
    const float* Wout      = (const float*)d_in[5];
    const float* bout      = (const float*)d_in[6];
    const float* W1        = (const float*)d_in[7];
    const float* b1        = (const float*)d_in[8];
    const float* W2        = (const float*)d_in[9];
    const float* b2        = (const float*)d_in[10];
    const float* ln_g      = (const float*)d_in[11];
    const float* ln_b      = (const float*)d_in[12];

    float* out        = (float*)d_out;
    float* hidden_out = out + (size_t)M_ * D_;

    float *buf0, *buf1, *buf2, *wT;
    cudaGetSymbolAddress((void**)&buf0, g_buf0);
    cudaGetSymbolAddress((void**)&buf1, g_buf1);
    cudaGetSymbolAddress((void**)&buf2, g_buf2);
    cudaGetSymbolAddress((void**)&wT,   g_wT);

    cudaFuncSetAttribute(tgemm_gates,       cudaFuncAttributeMaxDynamicSharedMemorySize, GEMM_SMEM);
    cudaFuncSetAttribute(tgemm<MODE_BIAS>,  cudaFuncAttributeMaxDynamicSharedMemorySize, GEMM_SMEM);
    cudaFuncSetAttribute(tgemm<MODE_GELU>,  cudaFuncAttributeMaxDynamicSharedMemorySize, GEMM_SMEM);
    cudaFuncSetAttribute(tgemm<MODE_RESID>, cudaFuncAttributeMaxDynamicSharedMemorySize, GEMM_SMEM);
    cudaFuncSetAttribute(scan_pass2, cudaFuncAttributeMaxDynamicSharedMemorySize, 2 * NC * 128 * 4);

    transpose_tf32<<<dim3(32, 32, 5), dim3(32, 8)>>>(
        Win, Win + (size_t)K_ * D_, Wout, W1, W2, wT);
    cvt_x_kernel<<<(M_ * K_) / (256 * 4), 256>>>(x, buf2);

    dim3 grid(D_ / BNm, M_ / BMm);        // (8, 128)
    dim3 grid_g(D_ / BNm, M_ / BMm, 2);   // both gates in one launch

    // v -> buf0 ; f -> buf1
    tgemm_gates<<<grid_g, 256, GEMM_SMEM>>>(buf2, wT, bin_, rnn_start, buf0, buf1);

    // chunked scan -> hs (tf32 bits) in buf2, hT -> hidden_out
    scan_pass1<<<(B_ * NC * D_) / 256, 256>>>(buf0, buf1);
    scan_pass2<<<32, 256, 2 * NC * 128 * 4>>>(hidden, hidden_out);
    scan_pass3<<<(B_ * NC * D_) / 256, 256>>>(buf0, buf1, buf2);

    // out = hs@Wout + bout -> buf0 (fp32) + buf1 (tf32 copy)
    tgemm<MODE_BIAS><<<grid, 256, GEMM_SMEM>>>(buf2, wT + 2 * (size_t)K_ * D_, bout, nullptr, buf0, buf1);
    // x_ = gelu(out@W1 + b1) -> buf2 (tf32 bits)
    tgemm<MODE_GELU><<<grid, 256, GEMM_SMEM>>>(buf1, wT + 3 * (size_t)K_ * D_, b1,   nullptr, buf2, nullptr);
    // z = x_@W2 + b2 + out -> buf1 (fp32)
    tgemm<MODE_RESID><<<grid, 256, GEMM_SMEM>>>(buf2, wT + 4 * (size_t)K_ * D_, b2,  buf0,    buf1, nullptr);
    // out = LN(z)
    ln_kernel<<<M_, 256>>>(buf1, ln_g, ln_b, out);
}

// round 6
// speedup vs baseline: 3.9976x; 1.0684x over previous
#include <cuda_runtime.h>
#include <math.h>
#include <stdint.h>

// Problem dims (fixed per setup_inputs)
#define B_   4
#define T_   4096
#define K_   1024          // Din == D == 1024
#define D_   1024
#define M_   (B_*T_)       // 16384

// ---------------- scratch (device globals; no allocations allowed) ---------
__device__ float g_buf0[(size_t)M_ * D_];   // 64 MB
__device__ float g_buf1[(size_t)M_ * D_];   // 64 MB
__device__ float g_buf2[(size_t)M_ * D_];   // 64 MB
__device__ float g_wT[(size_t)5 * K_ * D_]; // 20 MB transposed + tf32-rounded weights

#define CHUNK 32
#define NC    (T_/CHUNK)    // 128
__device__ float g_cA[B_*NC*D_];
__device__ float g_cP[B_*NC*D_];
__device__ float g_cC[B_*NC*D_];

// ---------------- helpers ----------------------------------------------------
__device__ __forceinline__ uint32_t cvt_tf32(float x) {
    uint32_t t; asm("cvt.rna.tf32.f32 %0, %1;" : "=r"(t) : "f"(x)); return t;
}
__device__ __forceinline__ uint32_t smem_u32(const void* p) {
    uint32_t a;
    asm("{ .reg .u64 t; cvta.to.shared.u64 t, %1; cvt.u32.u64 %0, t; }" : "=r"(a) : "l"(p));
    return a;
}
__device__ __forceinline__ void cp_async16(uint32_t saddr, const void* gptr) {
    asm volatile("cp.async.cg.shared.global [%0], [%1], 16;" :: "r"(saddr), "l"(gptr));
}
#define CP_COMMIT() asm volatile("cp.async.commit_group;" ::: "memory")
#define CP_WAIT1()  asm volatile("cp.async.wait_group 1;"  ::: "memory")
#define CP_WAIT0()  asm volatile("cp.async.wait_group 0;"  ::: "memory")

#define LDSM_X4(r0, r1, r2, r3, addr) \
    asm volatile("ldmatrix.sync.aligned.m8n8.x4.shared.b16 {%0,%1,%2,%3}, [%4];" \
                 : "=r"(r0), "=r"(r1), "=r"(r2), "=r"(r3) : "r"(addr))

__device__ __forceinline__ void mma_tf32(float c[4], const uint32_t a[4],
                                         uint32_t b0, uint32_t b1) {
    asm volatile(
        "mma.sync.aligned.m16n8k8.row.col.f32.tf32.tf32.f32 "
        "{%0,%1,%2,%3}, {%4,%5,%6,%7}, {%8,%9}, {%0,%1,%2,%3};"
        : "+f"(c[0]), "+f"(c[1]), "+f"(c[2]), "+f"(c[3])
        : "r"(a[0]), "r"(a[1]), "r"(a[2]), "r"(a[3]), "r"(b0), "r"(b1));
}

// ---------------- tf32 mma.sync GEMM core ------------------------------------
// A [M,1024] tf32 bits; Bt [N,K] tf32 bits (N-major). CTA 128x128, BK=32,
// 3-stage cp.async; 8 warps (2M x 4N), warp 64x32; LDSM + register double-buffer.

#define BMm 128
#define BNm 128
#define BKm 32
#define STEPSm (K_/BKm)        // 32
#define SROW  36               // padded row stride (words)
#define STAGE_WORDS (BMm*SROW)
#define STAGE_B (STAGE_WORDS*4)
#define NSTG 3
#define GEMM_SMEM (2*NSTG*STAGE_B)   // 110592 B

enum { MODE_TANH = 0, MODE_SIGF = 1, MODE_BIAS = 2, MODE_GELU = 3, MODE_RESID = 4 };

struct Frag { float acc[4][4][4]; };

__device__ __forceinline__ void gemm_mainloop(
    const float* __restrict__ Ab, const float* __restrict__ Bb,
    uint32_t sbase, int tid, int lane, int wm, int wn, Frag& fr)
{
    const uint32_t aB = sbase;
    const uint32_t bB = sbase + NSTG * STAGE_B;

    // cp.async mapping: 4 x 16B per matrix per stage per thread
    const int r0 = tid >> 3;
    const int c4 = (tid & 7) << 2;
    const uint32_t soff0 = (uint32_t)(r0 * SROW + c4) * 4;

    // LDSM per-lane offsets (bytes within a stage)
    const int rr = lane & 7;
    const int a_row8  = (lane >> 3) & 1;
    const int a_khalf = (lane >> 4) & 1;
    uint32_t aoff[4];
#pragma unroll
    for (int mi = 0; mi < 4; mi++)
        aoff[mi] = (uint32_t)((wm * 64 + mi * 16 + a_row8 * 8 + rr) * SROW + a_khalf * 4) * 4;
    const int b_khalf = (lane >> 3) & 1;
    const int b_n8    = (lane >> 4) & 1;
    uint32_t boff[2];
#pragma unroll
    for (int j = 0; j < 2; j++)
        boff[j] = (uint32_t)((wn * 32 + j * 16 + b_n8 * 8 + rr) * SROW + b_khalf * 4) * 4;

#pragma unroll
    for (int mi = 0; mi < 4; mi++)
#pragma unroll
        for (int ni = 0; ni < 4; ni++)
#pragma unroll
            for (int q = 0; q < 4; q++) fr.acc[mi][ni][q] = 0.f;

    uint32_t af[2][4][4];   // double-buffered A fragments
    uint32_t bq[2][2][4];   // double-buffered B fragments

#define ISSUE_STAGE(S) do {                                                     \
        const int _k0 = (S) * BKm;                                              \
        const uint32_t _sa = aB + ((S) % NSTG) * STAGE_B + soff0;               \
        const uint32_t _sb = bB + ((S) % NSTG) * STAGE_B + soff0;               \
        _Pragma("unroll")                                                       \
        for (int j = 0; j < 4; j++) {                                           \
            const size_t go = (size_t)(r0 + 32 * j) * K_ + _k0 + c4;            \
            const uint32_t so = (uint32_t)(32 * j * SROW) * 4;                  \
            cp_async16(_sa + so, Ab + go);                                      \
            cp_async16(_sb + so, Bb + go);                                      \
        }                                                                       \
    } while (0)

#define LOAD_FRAGS(SLOT, SA, SB, KO) do {                                       \
        _Pragma("unroll")                                                       \
        for (int mi = 0; mi < 4; mi++)                                          \
            LDSM_X4(af[SLOT][mi][0], af[SLOT][mi][1],                           \
                    af[SLOT][mi][2], af[SLOT][mi][3], (SA) + aoff[mi] + (KO));  \
        _Pragma("unroll")                                                       \
        for (int j = 0; j < 2; j++)                                             \
            LDSM_X4(bq[SLOT][j][0], bq[SLOT][j][1],                             \
                    bq[SLOT][j][2], bq[SLOT][j][3], (SB) + boff[j] + (KO));     \
    } while (0)

    ISSUE_STAGE(0); CP_COMMIT();
    ISSUE_STAGE(1); CP_COMMIT();
    CP_WAIT1();
    __syncthreads();

    uint32_t sa = aB, sb = bB;
    LOAD_FRAGS(0, sa, sb, 0);

    for (int s = 0; s < STEPSm; s++) {
#pragma unroll
        for (int ks = 0; ks < 4; ks++) {
            if (ks < 3) {
                LOAD_FRAGS((ks + 1) & 1, sa, sb, (uint32_t)(ks + 1) * 32);
            } else if (s + 1 < STEPSm) {
                if (s + 2 < STEPSm) { ISSUE_STAGE(s + 2); CP_COMMIT(); CP_WAIT1(); }
                else                { CP_WAIT0(); }
                __syncthreads();
                sa = aB + ((s + 1) % NSTG) * STAGE_B;
                sb = bB + ((s + 1) % NSTG) * STAGE_B;
                LOAD_FRAGS(0, sa, sb, 0);
            }
            const int p = ks & 1;
#pragma unroll
            for (int mi = 0; mi < 4; mi++)
#pragma unroll
                for (int ni = 0; ni < 4; ni++)
                    mma_tf32(fr.acc[mi][ni], af[p][mi],
                             bq[p][ni >> 1][(ni & 1) * 2],
                             bq[p][ni >> 1][(ni & 1) * 2 + 1]);
        }
    }
#undef ISSUE_STAGE
#undef LOAD_FRAGS
}

// ---- chain GEMMs (BIAS / GELU / RESID) --------------------------------------
template <int MODE>
__global__ __launch_bounds__(256)
void tgemm(const float* __restrict__ A, const float* __restrict__ Bt,
           const float* __restrict__ bias, const float* __restrict__ extra,
           float* __restrict__ C, float* __restrict__ C2)
{
    extern __shared__ float smf[];
    const uint32_t sbase = smem_u32(smf);
    const int tid = threadIdx.x, lane = tid & 31, wid = tid >> 5;
    const int wm = wid >> 2, wn = wid & 3;
    const int bn = blockIdx.x, bm = blockIdx.y;

    Frag fr;
    gemm_mainloop(A + (size_t)bm * BMm * K_, Bt + (size_t)bn * BNm * K_,
                  sbase, tid, lane, wm, wn, fr);

    const int r_base = bm * BMm + wm * 64 + (lane >> 2);
    const int c_base = bn * BNm + wn * 32 + ((lane & 3) << 1);
#pragma unroll
    for (int mi = 0; mi < 4; mi++) {
        const int gr0 = r_base + mi * 16;
        const int gr1 = gr0 + 8;
#pragma unroll
        for (int ni = 0; ni < 4; ni++) {
            const int gc = c_base + ni * 8;
            float b0 = bias[gc], b1 = bias[gc + 1];
            float v0 = fr.acc[mi][ni][0] + b0;
            float v1 = fr.acc[mi][ni][1] + b1;
            float v2 = fr.acc[mi][ni][2] + b0;
            float v3 = fr.acc[mi][ni][3] + b1;
            if (MODE == MODE_GELU) {
                v0 = 0.5f * v0 * (1.f + erff(v0 * 0.70710678118654752f));
                v1 = 0.5f * v1 * (1.f + erff(v1 * 0.70710678118654752f));
                v2 = 0.5f * v2 * (1.f + erff(v2 * 0.70710678118654752f));
                v3 = 0.5f * v3 * (1.f + erff(v3 * 0.70710678118654752f));
                v0 = __uint_as_float(cvt_tf32(v0));
                v1 = __uint_as_float(cvt_tf32(v1));
                v2 = __uint_as_float(cvt_tf32(v2));
                v3 = __uint_as_float(cvt_tf32(v3));
            } else if (MODE == MODE_RESID) {
                const float2 e0 = *reinterpret_cast<const float2*>(extra + (size_t)gr0 * D_ + gc);
                const float2 e1 = *reinterpret_cast<const float2*>(extra + (size_t)gr1 * D_ + gc);
                v0 += e0.x; v1 += e0.y; v2 += e1.x; v3 += e1.y;
            }
            *reinterpret_cast<float2*>(C + (size_t)gr0 * D_ + gc) = make_float2(v0, v1);
            *reinterpret_cast<float2*>(C + (size_t)gr1 * D_ + gc) = make_float2(v2, v3);
            if (MODE == MODE_BIAS) {
                float t0 = __uint_as_float(cvt_tf32(v0));
                float t1 = __uint_as_float(cvt_tf32(v1));
                float t2 = __uint_as_float(cvt_tf32(v2));
                float t3 = __uint_as_float(cvt_tf32(v3));
                *reinterpret_cast<float2*>(C2 + (size_t)gr0 * D_ + gc) = make_float2(t0, t1);
                *reinterpret_cast<float2*>(C2 + (size_t)gr1 * D_ + gc) = make_float2(t2, t3);
            }
        }
    }
}

// ---- fused gate GEMMs: z=0 -> tanh -> Cv ; z=1 -> sigmoid*(1-rs) -> Cf ------
__global__ __launch_bounds__(256)
void tgemm_gates(const float* __restrict__ A, const float* __restrict__ Wt,
                 const float* __restrict__ bin, const float* __restrict__ rnn_start,
                 float* __restrict__ Cv, float* __restrict__ Cf)
{
    extern __shared__ float smf[];
    const uint32_t sbase = smem_u32(smf);
    const int tid = threadIdx.x, lane = tid & 31, wid = tid >> 5;
    const int wm = wid >> 2, wn = wid & 3;
    const int bn = blockIdx.x, bm = blockIdx.y, z = blockIdx.z;

    const float* Bt   = Wt + (size_t)z * K_ * D_;
    const float* bias = bin + z * D_;

    Frag fr;
    gemm_mainloop(A + (size_t)bm * BMm * K_, Bt + (size_t)bn * BNm * K_,
                  sbase, tid, lane, wm, wn, fr);

    float* C = z ? Cf : Cv;
    const int r_base = bm * BMm + wm * 64 + (lane >> 2);
    const int c_base = bn * BNm + wn * 32 + ((lane & 3) << 1);
#pragma unroll
    for (int mi = 0; mi < 4; mi++) {
        const int gr0 = r_base + mi * 16;
        const int gr1 = gr0 + 8;
        float rs0 = 0.f, rs1 = 0.f;
        if (z) { rs0 = rnn_start[gr0]; rs1 = rnn_start[gr1]; }
#pragma unroll
        for (int ni = 0; ni < 4; ni++) {
            const int gc = c_base + ni * 8;
            float b0 = bias[gc], b1 = bias[gc + 1];
            float v0 = fr.acc[mi][ni][0] + b0;
            float v1 = fr.acc[mi][ni][1] + b1;
            float v2 = fr.acc[mi][ni][2] + b0;
            float v3 = fr.acc[mi][ni][3] + b1;
            if (z == 0) {
                v0 = tanhf(v0); v1 = tanhf(v1); v2 = tanhf(v2); v3 = tanhf(v3);
            } else {
                v0 = (1.f - rs0) / (1.f + expf(-v0));
                v1 = (1.f - rs0) / (1.f + expf(-v1));
                v2 = (1.f - rs1) / (1.f + expf(-v2));
                v3 = (1.f - rs1) / (1.f + expf(-v3));
            }
            *reinterpret_cast<float2*>(C + (size_t)gr0 * D_ + gc) = make_float2(v0, v1);
            *reinterpret_cast<float2*>(C + (size_t)gr1 * D_ + gc) = make_float2(v2, v3);
        }
    }
}

// ---------------- x -> tf32-rounded copy ------------------------------------
__global__ void cvt_x_kernel(const float* __restrict__ x, float* __restrict__ xt)
{
    int i = blockIdx.x * blockDim.x + threadIdx.x;
    float4 v = reinterpret_cast<const float4*>(x)[i];
    float4 o;
    o.x = __uint_as_float(cvt_tf32(v.x));
    o.y = __uint_as_float(cvt_tf32(v.y));
    o.z = __uint_as_float(cvt_tf32(v.z));
    o.w = __uint_as_float(cvt_tf32(v.w));
    reinterpret_cast<float4*>(xt)[i] = o;
}

// ---------------- weight transpose + tf32 rounding --------------------------
__global__ void transpose_tf32(const float* __restrict__ s0, const float* __restrict__ s1,
                               const float* __restrict__ s2, const float* __restrict__ s3,
                               const float* __restrict__ s4, float* __restrict__ dst)
{
    __shared__ float tile[32][33];
    const int z = blockIdx.z;
    const float* src = (z == 0) ? s0 : (z == 1) ? s1 : (z == 2) ? s2 : (z == 3) ? s3 : s4;
    float* d = dst + (size_t)z * K_ * D_;
    const int n0 = blockIdx.x * 32, k0 = blockIdx.y * 32;
    const int tx = threadIdx.x, ty = threadIdx.y;
#pragma unroll
    for (int r = 0; r < 32; r += 8)
        tile[ty + r][tx] = src[(size_t)(k0 + ty + r) * D_ + n0 + tx];
    __syncthreads();
#pragma unroll
    for (int r = 0; r < 32; r += 8) {
        uint32_t t = cvt_tf32(tile[tx][ty + r]);
        d[(size_t)(n0 + ty + r) * K_ + k0 + tx] = __uint_as_float(t);
    }
}

// ---------------- chunked scan ----------------------------------------------
__global__ void scan_pass1(const float* __restrict__ V, const float* __restrict__ F)
{
    int idx = blockIdx.x * blockDim.x + threadIdx.x;
    int d = idx % D_;
    int c = (idx / D_) % NC;
    int b = idx / (D_ * NC);
    size_t base = ((size_t)b * T_ + (size_t)c * CHUNK) * D_ + d;
    float A = 1.f, h = 0.f;
#pragma unroll 8
    for (int t = 0; t < CHUNK; t++) {
        float f = F[base + (size_t)t * D_];
        float v = V[base + (size_t)t * D_];
        A *= f;
        h = f * h + (1.f - f) * v;
    }
    g_cA[idx] = A;
    g_cP[idx] = h;
}

__global__ void scan_pass2(const float* __restrict__ hidden, float* __restrict__ hT_out)
{
    extern __shared__ float sh[];
    float* sA = sh;
    float* sP = sh + NC * 128;
    const int blk = blockIdx.x;
    const int b   = blk >> 3;
    const int d0  = (blk & 7) * 128;
#pragma unroll 4
    for (int j = 0; j < 64; j++) {
        int i  = threadIdx.x + 256 * j;
        int c  = i >> 7, dd = i & 127;
        size_t g = ((size_t)b * NC + c) * D_ + d0 + dd;
        sA[i] = g_cA[g];
        sP[i] = g_cP[g];
    }
    __syncthreads();
    if (threadIdx.x < 128) {
        const int dd = threadIdx.x;
        float h = hidden[(size_t)b * D_ + d0 + dd];
        for (int c = 0; c < NC; c++) {
            g_cC[((size_t)b * NC + c) * D_ + d0 + dd] = h;
            h = sA[c * 128 + dd] * h + sP[c * 128 + dd];
        }
        hT_out[(size_t)b * D_ + d0 + dd] = h;
    }
}

__global__ void scan_pass3(const float* __restrict__ V, const float* __restrict__ F,
                           float* __restrict__ HS)
{
    int idx = blockIdx.x * blockDim.x + threadIdx.x;
    int d = idx % D_;
    int c = (idx / D_) % NC;
    int b = idx / (D_ * NC);
    size_t base = ((size_t)b * T_ + (size_t)c * CHUNK) * D_ + d;
    float h = g_cC[idx];
#pragma unroll 8
    for (int t = 0; t < CHUNK; t++) {
        float f = F[base + (size_t)t * D_];
        float v = V[base + (size_t)t * D_];
        h = f * h + (1.f - f) * v;
        HS[base + (size_t)t * D_] = __uint_as_float(cvt_tf32(h));
    }
}

// ---------------- LayerNorm ---------------------------------------------------
__global__ __launch_bounds__(256)
void ln_kernel(const float* __restrict__ Z, const float* __restrict__ g,
               const float* __restrict__ b, float* __restrict__ out)
{
    int row = blockIdx.x;
    int t = threadIdx.x;
    float4 x = reinterpret_cast<const float4*>(Z + (size_t)row * D_)[t];
    float s  = x.x + x.y + x.z + x.w;
    float ss = x.x * x.x + x.y * x.y + x.z * x.z + x.w * x.w;
#pragma unroll
    for (int o = 16; o > 0; o >>= 1) {
        s  += __shfl_xor_sync(0xFFFFFFFFu, s, o);
        ss += __shfl_xor_sync(0xFFFFFFFFu, ss, o);
    }
    __shared__ float sh_s[8], sh_ss[8];
    int w = t >> 5, l = t & 31;
    if (l == 0) { sh_s[w] = s; sh_ss[w] = ss; }
    __syncthreads();
    if (w == 0) {
        s  = (l < 8) ? sh_s[l]  : 0.f;
        ss = (l < 8) ? sh_ss[l] : 0.f;
#pragma unroll
        for (int o = 4; o > 0; o >>= 1) {
            s  += __shfl_xor_sync(0xFFFFFFFFu, s, o);
            ss += __shfl_xor_sync(0xFFFFFFFFu, ss, o);
        }
        if (l == 0) { sh_s[0] = s; sh_ss[0] = ss; }
    }
    __syncthreads();
    float mean = sh_s[0] * (1.f / D_);
    float var  = sh_ss[0] * (1.f / D_) - mean * mean;
    float rstd = rsqrtf(var + 1e-5f);
    float4 gg = reinterpret_cast<const float4*>(g)[t];
    float4 bb = reinterpret_cast<const float4*>(b)[t];
    float4 y;
    y.x = (x.x - mean) * rstd * gg.x + bb.x;
    y.y = (x.y - mean) * rstd * gg.y + bb.y;
    y.z = (x.z - mean) * rstd * gg.z + bb.z;
    y.w = (x.w - mean) * rstd * gg.w + bb.w;
    reinterpret_cast<float4*>(out + (size_t)row * D_)[t] = y;
}

// ---------------- launch -------------------------------------------------------
extern "C" void kernel_launch(void* const* d_in, const int* in_sizes, int n_in,
                              void* d_out, int out_size)
{
    const float* x         = (const float*)d_in[0];
    const float* hidden    = (const float*)d_in[1];
    const float* rnn_start = (const float*)d_in[2];
    const float* Win       = (const float*)d_in[3];
    const float* bin_      = (const float*)d_in[4];
    const float* Wout      = (const float*)d_in[5];
    const float* bout      = (const float*)d_in[6];
    const float* W1        = (const float*)d_in[7];
    const float* b1        = (const float*)d_in[8];
    const float* W2        = (const float*)d_in[9];
    const float* b2        = (const float*)d_in[10];
    const float* ln_g      = (const float*)d_in[11];
    const float* ln_b      = (const float*)d_in[12];

    float* out        = (float*)d_out;
    float* hidden_out = out + (size_t)M_ * D_;

    float *buf0, *buf1, *buf2, *wT;
    cudaGetSymbolAddress((void**)&buf0, g_buf0);
    cudaGetSymbolAddress((void**)&buf1, g_buf1);
    cudaGetSymbolAddress((void**)&buf2, g_buf2);
    cudaGetSymbolAddress((void**)&wT,   g_wT);

    cudaFuncSetAttribute(tgemm_gates,       cudaFuncAttributeMaxDynamicSharedMemorySize, GEMM_SMEM);
    cudaFuncSetAttribute(tgemm<MODE_BIAS>,  cudaFuncAttributeMaxDynamicSharedMemorySize, GEMM_SMEM);
    cudaFuncSetAttribute(tgemm<MODE_GELU>,  cudaFuncAttributeMaxDynamicSharedMemorySize, GEMM_SMEM);
    cudaFuncSetAttribute(tgemm<MODE_RESID>, cudaFuncAttributeMaxDynamicSharedMemorySize, GEMM_SMEM);
    cudaFuncSetAttribute(scan_pass2, cudaFuncAttributeMaxDynamicSharedMemorySize, 2 * NC * 128 * 4);

    transpose_tf32<<<dim3(32, 32, 5), dim3(32, 8)>>>(
        Win, Win + (size_t)K_ * D_, Wout, W1, W2, wT);
    cvt_x_kernel<<<(M_ * K_) / (256 * 4), 256>>>(x, buf2);

    dim3 grid(D_ / BNm, M_ / BMm);        // (8, 128)
    dim3 grid_g(D_ / BNm, M_ / BMm, 2);   // both gates in one launch

    // v -> buf0 ; f -> buf1
    tgemm_gates<<<grid_g, 256, GEMM_SMEM>>>(buf2, wT, bin_, rnn_start, buf0, buf1);

    // chunked scan -> hs (tf32 bits) in buf2, hT -> hidden_out
    scan_pass1<<<(B_ * NC * D_) / 256, 256>>>(buf0, buf1);
    scan_pass2<<<32, 256, 2 * NC * 128 * 4>>>(hidden, hidden_out);
    scan_pass3<<<(B_ * NC * D_) / 256, 256>>>(buf0, buf1, buf2);

    // out = hs@Wout + bout -> buf0 (fp32) + buf1 (tf32 copy)
    tgemm<MODE_BIAS><<<grid, 256, GEMM_SMEM>>>(buf2, wT + 2 * (size_t)K_ * D_, bout, nullptr, buf0, buf1);
    // x_ = gelu(out@W1 + b1) -> buf2 (tf32 bits)
    tgemm<MODE_GELU><<<grid, 256, GEMM_SMEM>>>(buf1, wT + 3 * (size_t)K_ * D_, b1,   nullptr, buf2, nullptr);
    // z = x_@W2 + b2 + out -> buf1 (fp32)
    tgemm<MODE_RESID><<<grid, 256, GEMM_SMEM>>>(buf2, wT + 4 * (size_t)K_ * D_, b2,  buf0,    buf1, nullptr);
    // out = LN(z)
    ln_kernel<<<M_, 256>>>(buf1, ln_g, ln_b, out);
}

// round 7
// speedup vs baseline: 4.7779x; 1.1952x over previous
#include <cuda_runtime.h>
#include <math.h>
#include <stdint.h>

// Problem dims (fixed per setup_inputs)
#define B_   4
#define T_   4096
#define K_   1024          // Din == D == 1024
#define D_   1024
#define M_   (B_*T_)       // 16384

// ---------------- scratch (device globals; no allocations allowed) ---------
__device__ float g_buf0[(size_t)M_ * D_];   // 64 MB
__device__ float g_buf1[(size_t)M_ * D_];   // 64 MB
__device__ float g_buf2[(size_t)M_ * D_];   // 64 MB
__device__ float g_wT[(size_t)5 * K_ * D_]; // 20 MB transposed + tf32-rounded weights

#define CHUNK 32
#define NC    (T_/CHUNK)    // 128
__device__ float g_cA[B_*NC*D_];
__device__ float g_cP[B_*NC*D_];
__device__ float g_cC[B_*NC*D_];

// ---------------- helpers ----------------------------------------------------
__device__ __forceinline__ uint32_t cvt_tf32(float x) {
    uint32_t t; asm("cvt.rna.tf32.f32 %0, %1;" : "=r"(t) : "f"(x)); return t;
}
__device__ __forceinline__ uint32_t smem_u32(const void* p) {
    uint32_t a;
    asm("{ .reg .u64 t; cvta.to.shared.u64 t, %1; cvt.u32.u64 %0, t; }" : "=r"(a) : "l"(p));
    return a;
}
__device__ __forceinline__ void cp_async16(uint32_t saddr, const void* gptr) {
    asm volatile("cp.async.cg.shared.global [%0], [%1], 16;" :: "r"(saddr), "l"(gptr));
}
#define CP_COMMIT() asm volatile("cp.async.commit_group;" ::: "memory")
#define CP_WAIT1()  asm volatile("cp.async.wait_group 1;"  ::: "memory")
#define CP_WAIT0()  asm volatile("cp.async.wait_group 0;"  ::: "memory")

#define LDSM_X4(r0, r1, r2, r3, addr) \
    asm volatile("ldmatrix.sync.aligned.m8n8.x4.shared.b16 {%0,%1,%2,%3}, [%4];" \
                 : "=r"(r0), "=r"(r1), "=r"(r2), "=r"(r3) : "r"(addr))

__device__ __forceinline__ void mma_tf32(float c[4], const uint32_t a[4],
                                         uint32_t b0, uint32_t b1) {
    asm volatile(
        "mma.sync.aligned.m16n8k8.row.col.f32.tf32.tf32.f32 "
        "{%0,%1,%2,%3}, {%4,%5,%6,%7}, {%8,%9}, {%0,%1,%2,%3};"
        : "+f"(c[0]), "+f"(c[1]), "+f"(c[2]), "+f"(c[3])
        : "r"(a[0]), "r"(a[1]), "r"(a[2]), "r"(a[3]), "r"(b0), "r"(b1));
}

// ---------------- tf32 mma.sync GEMM core ------------------------------------
// A [M,1024] tf32 bits; Bt [N,K] tf32 bits (N-major). CTA 128x128, BK=32,
// 3-stage cp.async; 8 warps (2M x 4N), warp 64x32; LDSM + register double-buffer.
// SMEM: XOR-swizzled 128B rows (no padding) -> stage 16KB, 2 CTAs/SM.

#define BMm 128
#define BNm 128
#define BKm 32
#define STEPSm (K_/BKm)        // 32
#define STAGE_B 16384          // 128 rows * 128 bytes
#define NSTG 3
#define GEMM_SMEM (2*NSTG*STAGE_B)   // 98304 B

enum { MODE_TANH = 0, MODE_SIGF = 1, MODE_BIAS = 2, MODE_GELU = 3, MODE_RESID = 4 };

struct Frag { float acc[4][4][4]; };

__device__ __forceinline__ void gemm_mainloop(
    const float* __restrict__ Ab, const float* __restrict__ Bb,
    uint32_t sbase, int tid, int lane, int wm, int wn, Frag& fr)
{
    const uint32_t aB = sbase;
    const uint32_t bB = sbase + NSTG * STAGE_B;

    // cp.async mapping: 4 x 16B per matrix per stage per thread, swizzled cols
    const int r0 = tid >> 3;
    const int c4 = (tid & 7) << 2;
    const uint32_t soff0 = (uint32_t)(r0 << 7) + (((uint32_t)c4 << 2) ^ (((uint32_t)r0 & 7) << 4));

    // LDSM per-lane constants
    const int rr = lane & 7;
    const uint32_t swz = (uint32_t)rr << 4;              // row-phase swizzle
    const uint32_t akoff = (uint32_t)((lane >> 4) & 1) << 4;   // A k-half
    const uint32_t bkoff = (uint32_t)((lane >> 3) & 1) << 4;   // B k-half
    const int a_row8 = (lane >> 3) & 1;
    const int b_n8   = (lane >> 4) & 1;
    uint32_t aoff[4];
#pragma unroll
    for (int mi = 0; mi < 4; mi++)
        aoff[mi] = (uint32_t)(wm * 64 + mi * 16 + a_row8 * 8 + rr) << 7;
    uint32_t boff[2];
#pragma unroll
    for (int j = 0; j < 2; j++)
        boff[j] = (uint32_t)(wn * 32 + j * 16 + b_n8 * 8 + rr) << 7;

#pragma unroll
    for (int mi = 0; mi < 4; mi++)
#pragma unroll
        for (int ni = 0; ni < 4; ni++)
#pragma unroll
            for (int q = 0; q < 4; q++) fr.acc[mi][ni][q] = 0.f;

    uint32_t af[2][4][4];   // double-buffered A fragments
    uint32_t bq[2][2][4];   // double-buffered B fragments

#define ISSUE_STAGE(S) do {                                                     \
        const int _k0 = (S) * BKm;                                              \
        const uint32_t _sa = aB + ((S) % NSTG) * STAGE_B + soff0;               \
        const uint32_t _sb = bB + ((S) % NSTG) * STAGE_B + soff0;               \
        _Pragma("unroll")                                                       \
        for (int j = 0; j < 4; j++) {                                           \
            const size_t go = (size_t)(r0 + 32 * j) * K_ + _k0 + c4;            \
            const uint32_t so = (uint32_t)(32 * j) << 7;                        \
            cp_async16(_sa + so, Ab + go);                                      \
            cp_async16(_sb + so, Bb + go);                                      \
        }                                                                       \
    } while (0)

#define LOAD_FRAGS(SLOT, SA, SB, KO) do {                                       \
        const uint32_t _ax = ((KO) + akoff) ^ swz;                              \
        const uint32_t _bx = ((KO) + bkoff) ^ swz;                              \
        _Pragma("unroll")                                                       \
        for (int mi = 0; mi < 4; mi++)                                          \
            LDSM_X4(af[SLOT][mi][0], af[SLOT][mi][1],                           \
                    af[SLOT][mi][2], af[SLOT][mi][3], (SA) + aoff[mi] + _ax);   \
        _Pragma("unroll")                                                       \
        for (int j = 0; j < 2; j++)                                             \
            LDSM_X4(bq[SLOT][j][0], bq[SLOT][j][1],                             \
                    bq[SLOT][j][2], bq[SLOT][j][3], (SB) + boff[j] + _bx);      \
    } while (0)

    ISSUE_STAGE(0); CP_COMMIT();
    ISSUE_STAGE(1); CP_COMMIT();
    CP_WAIT1();
    __syncthreads();

    uint32_t sa = aB, sb = bB;
    LOAD_FRAGS(0, sa, sb, 0u);

    for (int s = 0; s < STEPSm; s++) {
#pragma unroll
        for (int ks = 0; ks < 4; ks++) {
            if (ks < 3) {
                LOAD_FRAGS((ks + 1) & 1, sa, sb, (uint32_t)(ks + 1) * 32);
            } else if (s + 1 < STEPSm) {
                if (s + 2 < STEPSm) { ISSUE_STAGE(s + 2); CP_COMMIT(); CP_WAIT1(); }
                else                { CP_WAIT0(); }
                __syncthreads();
                sa = aB + ((s + 1) % NSTG) * STAGE_B;
                sb = bB + ((s + 1) % NSTG) * STAGE_B;
                LOAD_FRAGS(0, sa, sb, 0u);
            }
            const int p = ks & 1;
#pragma unroll
            for (int mi = 0; mi < 4; mi++)
#pragma unroll
                for (int ni = 0; ni < 4; ni++)
                    mma_tf32(fr.acc[mi][ni], af[p][mi],
                             bq[p][ni >> 1][(ni & 1) * 2],
                             bq[p][ni >> 1][(ni & 1) * 2 + 1]);
        }
    }
#undef ISSUE_STAGE
#undef LOAD_FRAGS
}

// ---- chain GEMMs (BIAS / GELU / RESID) --------------------------------------
template <int MODE>
__global__ __launch_bounds__(256, 2)
void tgemm(const float* __restrict__ A, const float* __restrict__ Bt,
           const float* __restrict__ bias, const float* __restrict__ extra,
           float* __restrict__ C, float* __restrict__ C2)
{
    extern __shared__ float smf[];
    const uint32_t sbase = smem_u32(smf);
    const int tid = threadIdx.x, lane = tid & 31, wid = tid >> 5;
    const int wm = wid >> 2, wn = wid & 3;
    const int bn = blockIdx.x, bm = blockIdx.y;

    Frag fr;
    gemm_mainloop(A + (size_t)bm * BMm * K_, Bt + (size_t)bn * BNm * K_,
                  sbase, tid, lane, wm, wn, fr);

    const int r_base = bm * BMm + wm * 64 + (lane >> 2);
    const int c_base = bn * BNm + wn * 32 + ((lane & 3) << 1);
#pragma unroll
    for (int mi = 0; mi < 4; mi++) {
        const int gr0 = r_base + mi * 16;
        const int gr1 = gr0 + 8;
#pragma unroll
        for (int ni = 0; ni < 4; ni++) {
            const int gc = c_base + ni * 8;
            float b0 = bias[gc], b1 = bias[gc + 1];
            float v0 = fr.acc[mi][ni][0] + b0;
            float v1 = fr.acc[mi][ni][1] + b1;
            float v2 = fr.acc[mi][ni][2] + b0;
            float v3 = fr.acc[mi][ni][3] + b1;
            if (MODE == MODE_GELU) {
                v0 = 0.5f * v0 * (1.f + erff(v0 * 0.70710678118654752f));
                v1 = 0.5f * v1 * (1.f + erff(v1 * 0.70710678118654752f));
                v2 = 0.5f * v2 * (1.f + erff(v2 * 0.70710678118654752f));
                v3 = 0.5f * v3 * (1.f + erff(v3 * 0.70710678118654752f));
                v0 = __uint_as_float(cvt_tf32(v0));
                v1 = __uint_as_float(cvt_tf32(v1));
                v2 = __uint_as_float(cvt_tf32(v2));
                v3 = __uint_as_float(cvt_tf32(v3));
            } else if (MODE == MODE_RESID) {
                const float2 e0 = *reinterpret_cast<const float2*>(extra + (size_t)gr0 * D_ + gc);
                const float2 e1 = *reinterpret_cast<const float2*>(extra + (size_t)gr1 * D_ + gc);
                v0 += e0.x; v1 += e0.y; v2 += e1.x; v3 += e1.y;
            }
            *reinterpret_cast<float2*>(C + (size_t)gr0 * D_ + gc) = make_float2(v0, v1);
            *reinterpret_cast<float2*>(C + (size_t)gr1 * D_ + gc) = make_float2(v2, v3);
            if (MODE == MODE_BIAS) {
                float t0 = __uint_as_float(cvt_tf32(v0));
                float t1 = __uint_as_float(cvt_tf32(v1));
                float t2 = __uint_as_float(cvt_tf32(v2));
                float t3 = __uint_as_float(cvt_tf32(v3));
                *reinterpret_cast<float2*>(C2 + (size_t)gr0 * D_ + gc) = make_float2(t0, t1);
                *reinterpret_cast<float2*>(C2 + (size_t)gr1 * D_ + gc) = make_float2(t2, t3);
            }
        }
    }
}

// ---- fused gate GEMMs: z=0 -> tanh -> Cv ; z=1 -> sigmoid*(1-rs) -> Cf ------
__global__ __launch_bounds__(256, 2)
void tgemm_gates(const float* __restrict__ A, const float* __restrict__ Wt,
                 const float* __restrict__ bin, const float* __restrict__ rnn_start,
                 float* __restrict__ Cv, float* __restrict__ Cf)
{
    extern __shared__ float smf[];
    const uint32_t sbase = smem_u32(smf);
    const int tid = threadIdx.x, lane = tid & 31, wid = tid >> 5;
    const int wm = wid >> 2, wn = wid & 3;
    const int bn = blockIdx.x, bm = blockIdx.y, z = blockIdx.z;

    const float* Bt   = Wt + (size_t)z * K_ * D_;
    const float* bias = bin + z * D_;

    Frag fr;
    gemm_mainloop(A + (size_t)bm * BMm * K_, Bt + (size_t)bn * BNm * K_,
                  sbase, tid, lane, wm, wn, fr);

    float* C = z ? Cf : Cv;
    const int r_base = bm * BMm + wm * 64 + (lane >> 2);
    const int c_base = bn * BNm + wn * 32 + ((lane & 3) << 1);
#pragma unroll
    for (int mi = 0; mi < 4; mi++) {
        const int gr0 = r_base + mi * 16;
        const int gr1 = gr0 + 8;
        float rs0 = 0.f, rs1 = 0.f;
        if (z) { rs0 = rnn_start[gr0]; rs1 = rnn_start[gr1]; }
#pragma unroll
        for (int ni = 0; ni < 4; ni++) {
            const int gc = c_base + ni * 8;
            float b0 = bias[gc], b1 = bias[gc + 1];
            float v0 = fr.acc[mi][ni][0] + b0;
            float v1 = fr.acc[mi][ni][1] + b1;
            float v2 = fr.acc[mi][ni][2] + b0;
            float v3 = fr.acc[mi][ni][3] + b1;
            if (z == 0) {
                v0 = tanhf(v0); v1 = tanhf(v1); v2 = tanhf(v2); v3 = tanhf(v3);
            } else {
                v0 = (1.f - rs0) / (1.f + expf(-v0));
                v1 = (1.f - rs0) / (1.f + expf(-v1));
                v2 = (1.f - rs1) / (1.f + expf(-v2));
                v3 = (1.f - rs1) / (1.f + expf(-v3));
            }
            *reinterpret_cast<float2*>(C + (size_t)gr0 * D_ + gc) = make_float2(v0, v1);
            *reinterpret_cast<float2*>(C + (size_t)gr1 * D_ + gc) = make_float2(v2, v3);
        }
    }
}

// ---------------- x -> tf32-rounded copy ------------------------------------
__global__ void cvt_x_kernel(const float* __restrict__ x, float* __restrict__ xt)
{
    int i = blockIdx.x * blockDim.x + threadIdx.x;
    float4 v = reinterpret_cast<const float4*>(x)[i];
    float4 o;
    o.x = __uint_as_float(cvt_tf32(v.x));
    o.y = __uint_as_float(cvt_tf32(v.y));
    o.z = __uint_as_float(cvt_tf32(v.z));
    o.w = __uint_as_float(cvt_tf32(v.w));
    reinterpret_cast<float4*>(xt)[i] = o;
}

// ---------------- weight transpose + tf32 rounding --------------------------
__global__ void transpose_tf32(const float* __restrict__ s0, const float* __restrict__ s1,
                               const float* __restrict__ s2, const float* __restrict__ s3,
                               const float* __restrict__ s4, float* __restrict__ dst)
{
    __shared__ float tile[32][33];
    const int z = blockIdx.z;
    const float* src = (z == 0) ? s0 : (z == 1) ? s1 : (z == 2) ? s2 : (z == 3) ? s3 : s4;
    float* d = dst + (size_t)z * K_ * D_;
    const int n0 = blockIdx.x * 32, k0 = blockIdx.y * 32;
    const int tx = threadIdx.x, ty = threadIdx.y;
#pragma unroll
    for (int r = 0; r < 32; r += 8)
        tile[ty + r][tx] = src[(size_t)(k0 + ty + r) * D_ + n0 + tx];
    __syncthreads();
#pragma unroll
    for (int r = 0; r < 32; r += 8) {
        uint32_t t = cvt_tf32(tile[tx][ty + r]);
        d[(size_t)(n0 + ty + r) * K_ + k0 + tx] = __uint_as_float(t);
    }
}

// ---------------- chunked scan ----------------------------------------------
__global__ void scan_pass1(const float* __restrict__ V, const float* __restrict__ F)
{
    int idx = blockIdx.x * blockDim.x + threadIdx.x;
    int d = idx % D_;
    int c = (idx / D_) % NC;
    int b = idx / (D_ * NC);
    size_t base = ((size_t)b * T_ + (size_t)c * CHUNK) * D_ + d;
    float A = 1.f, h = 0.f;
#pragma unroll 8
    for (int t = 0; t < CHUNK; t++) {
        float f = F[base + (size_t)t * D_];
        float v = V[base + (size_t)t * D_];
        A *= f;
        h = f * h + (1.f - f) * v;
    }
    g_cA[idx] = A;
    g_cP[idx] = h;
}

__global__ void scan_pass2(const float* __restrict__ hidden, float* __restrict__ hT_out)
{
    extern __shared__ float sh[];
    float* sA = sh;
    float* sP = sh + NC * 128;
    const int blk = blockIdx.x;
    const int b   = blk >> 3;
    const int d0  = (blk & 7) * 128;
#pragma unroll 4
    for (int j = 0; j < 64; j++) {
        int i  = threadIdx.x + 256 * j;
        int c  = i >> 7, dd = i & 127;
        size_t g = ((size_t)b * NC + c) * D_ + d0 + dd;
        sA[i] = g_cA[g];
        sP[i] = g_cP[g];
    }
    __syncthreads();
    if (threadIdx.x < 128) {
        const int dd = threadIdx.x;
        float h = hidden[(size_t)b * D_ + d0 + dd];
        for (int c = 0; c < NC; c++) {
            g_cC[((size_t)b * NC + c) * D_ + d0 + dd] = h;
            h = sA[c * 128 + dd] * h + sP[c * 128 + dd];
        }
        hT_out[(size_t)b * D_ + d0 + dd] = h;
    }
}

__global__ void scan_pass3(const float* __restrict__ V, const float* __restrict__ F,
                           float* __restrict__ HS)
{
    int idx = blockIdx.x * blockDim.x + threadIdx.x;
    int d = idx % D_;
    int c = (idx / D_) % NC;
    int b = idx / (D_ * NC);
    size_t base = ((size_t)b * T_ + (size_t)c * CHUNK) * D_ + d;
    float h = g_cC[idx];
#pragma unroll 8
    for (int t = 0; t < CHUNK; t++) {
        float f = F[base + (size_t)t * D_];
        float v = V[base + (size_t)t * D_];
        h = f * h + (1.f - f) * v;
        HS[base + (size_t)t * D_] = __uint_as_float(cvt_tf32(h));
    }
}

// ---------------- LayerNorm ---------------------------------------------------
__global__ __launch_bounds__(256)
void ln_kernel(const float* __restrict__ Z, const float* __restrict__ g,
               const float* __restrict__ b, float* __restrict__ out)
{
    int row = blockIdx.x;
    int t = threadIdx.x;
    float4 x = reinterpret_cast<const float4*>(Z + (size_t)row * D_)[t];
    float s  = x.x + x.y + x.z + x.w;
    float ss = x.x * x.x + x.y * x.y + x.z * x.z + x.w * x.w;
#pragma unroll
    for (int o = 16; o > 0; o >>= 1) {
        s  += __shfl_xor_sync(0xFFFFFFFFu, s, o);
        ss += __shfl_xor_sync(0xFFFFFFFFu, ss, o);
    }
    __shared__ float sh_s[8], sh_ss[8];
    int w = t >> 5, l = t & 31;
    if (l == 0) { sh_s[w] = s; sh_ss[w] = ss; }
    __syncthreads();
    if (w == 0) {
        s  = (l < 8) ? sh_s[l]  : 0.f;
        ss = (l < 8) ? sh_ss[l] : 0.f;
#pragma unroll
        for (int o = 4; o > 0; o >>= 1) {
            s  += __shfl_xor_sync(0xFFFFFFFFu, s, o);
            ss += __shfl_xor_sync(0xFFFFFFFFu, ss, o);
        }
        if (l == 0) { sh_s[0] = s; sh_ss[0] = ss; }
    }
    __syncthreads();
    float mean = sh_s[0] * (1.f / D_);
    float var  = sh_ss[0] * (1.f / D_) - mean * mean;
    float rstd = rsqrtf(var + 1e-5f);
    float4 gg = reinterpret_cast<const float4*>(g)[t];
    float4 bb = reinterpret_cast<const float4*>(b)[t];
    float4 y;
    y.x = (x.x - mean) * rstd * gg.x + bb.x;
    y.y = (x.y - mean) * rstd * gg.y + bb.y;
    y.z = (x.z - mean) * rstd * gg.z + bb.z;
    y.w = (x.w - mean) * rstd * gg.w + bb.w;
    reinterpret_cast<float4*>(out + (size_t)row * D_)[t] = y;
}

// ---------------- launch -------------------------------------------------------
extern "C" void kernel_launch(void* const* d_in, const int* in_sizes, int n_in,
                              void* d_out, int out_size)
{
    const float* x         = (const float*)d_in[0];
    const float* hidden    = (const float*)d_in[1];
    const float* rnn_start = (const float*)d_in[2];
    const float* Win       = (const float*)d_in[3];
    const float* bin_      = (const float*)d_in[4];
    const float* Wout      = (const float*)d_in[5];
    const float* bout      = (const float*)d_in[6];
    const float* W1        = (const float*)d_in[7];
    const float* b1        = (const float*)d_in[8];
    const float* W2        = (const float*)d_in[9];
    const float* b2        = (const float*)d_in[10];
    const float* ln_g      = (const float*)d_in[11];
    const float* ln_b      = (const float*)d_in[12];

    float* out        = (float*)d_out;
    float* hidden_out = out + (size_t)M_ * D_;

    float *buf0, *buf1, *buf2, *wT;
    cudaGetSymbolAddress((void**)&buf0, g_buf0);
    cudaGetSymbolAddress((void**)&buf1, g_buf1);
    cudaGetSymbolAddress((void**)&buf2, g_buf2);
    cudaGetSymbolAddress((void**)&wT,   g_wT);

    cudaFuncSetAttribute(tgemm_gates,       cudaFuncAttributeMaxDynamicSharedMemorySize, GEMM_SMEM);
    cudaFuncSetAttribute(tgemm<MODE_BIAS>,  cudaFuncAttributeMaxDynamicSharedMemorySize, GEMM_SMEM);
    cudaFuncSetAttribute(tgemm<MODE_GELU>,  cudaFuncAttributeMaxDynamicSharedMemorySize, GEMM_SMEM);
    cudaFuncSetAttribute(tgemm<MODE_RESID>, cudaFuncAttributeMaxDynamicSharedMemorySize, GEMM_SMEM);
    cudaFuncSetAttribute(scan_pass2, cudaFuncAttributeMaxDynamicSharedMemorySize, 2 * NC * 128 * 4);

    transpose_tf32<<<dim3(32, 32, 5), dim3(32, 8)>>>(
        Win, Win + (size_t)K_ * D_, Wout, W1, W2, wT);
    cvt_x_kernel<<<(M_ * K_) / (256 * 4), 256>>>(x, buf2);

    dim3 grid(D_ / BNm, M_ / BMm);        // (8, 128)
    dim3 grid_g(D_ / BNm, M_ / BMm, 2);   // both gates in one launch

    // v -> buf0 ; f -> buf1
    tgemm_gates<<<grid_g, 256, GEMM_SMEM>>>(buf2, wT, bin_, rnn_start, buf0, buf1);

    // chunked scan -> hs (tf32 bits) in buf2, hT -> hidden_out
    scan_pass1<<<(B_ * NC * D_) / 256, 256>>>(buf0, buf1);
    scan_pass2<<<32, 256, 2 * NC * 128 * 4>>>(hidden, hidden_out);
    scan_pass3<<<(B_ * NC * D_) / 256, 256>>>(buf0, buf1, buf2);

    // out = hs@Wout + bout -> buf0 (fp32) + buf1 (tf32 copy)
    tgemm<MODE_BIAS><<<grid, 256, GEMM_SMEM>>>(buf2, wT + 2 * (size_t)K_ * D_, bout, nullptr, buf0, buf1);
    // x_ = gelu(out@W1 + b1) -> buf2 (tf32 bits)
    tgemm<MODE_GELU><<<grid, 256, GEMM_SMEM>>>(buf1, wT + 3 * (size_t)K_ * D_, b1,   nullptr, buf2, nullptr);
    // z = x_@W2 + b2 + out -> buf1 (fp32)
    tgemm<MODE_RESID><<<grid, 256, GEMM_SMEM>>>(buf2, wT + 4 * (size_t)K_ * D_, b2,  buf0,    buf1, nullptr);
    // out = LN(z)
    ln_kernel<<<M_, 256>>>(buf1, ln_g, ln_b, out);
}